// round 13
// baseline (speedup 1.0000x reference)
#include <cuda_runtime.h>
#include <cuda_bf16.h>

// GINE-conv network:
//   h = emb[x]; h = leaky_relu(gine(h, E1)); h2 = gine(h, E2); out = h2 @ h2.T
// N=8192, E=262144, dims 128 -> 64 -> 32, out 8192x8192 f32.
// R13 vs R12 (158.7us):
//   (1) edge1/edge2: weight staging via uint4 (was 8x LDG.32 per thread);
//   (2) edge2 Phase B: 2 edges per warp (half-warp x float4 covers a full
//       64-col h1 row) -> per-edge instruction count halves;
//   (3) prep kernels fused into one launch.

#define NN     8192
#define NE     262144
#define EMB    128
#define D1     64
#define D2     32
#define EPSF   1e-9f
#define SLOPEF 0.01f

__device__ __align__(16) float g_h[NN * EMB];
__device__ __align__(16) float g_agg1[NN * EMB];
__device__ __align__(16) float g_h1[NN * D1];
__device__ __align__(16) float g_agg2[NN * D1];
__device__ __align__(16) unsigned short g_h2hi[NN * D2];   // bf16 hi
__device__ __align__(16) unsigned short g_h2lo[NN * D2];   // bf16 lo residual
__device__ __align__(16) unsigned short g_w1hi[EMB * 16];  // E1w^T hi [n][k]
__device__ __align__(16) unsigned short g_w1lo[EMB * 16];  // E1w^T lo [n][k]
__device__ __align__(16) unsigned short g_w2hi[D1 * 16];   // E2w^T hi [n][k]
__device__ __align__(16) unsigned short g_w2lo[D1 * 16];   // E2w^T lo [n][k]
__device__ __align__(16) unsigned short g_w1bh[D1 * EMB];  // W1^T hi [n][k]
__device__ __align__(16) unsigned short g_w1bl[D1 * EMB];  // W1^T lo [n][k]
__device__ int g_x[NN];
__device__ int g_src[NE];
__device__ int g_dst[NE];

__device__ __forceinline__ void ldx4(unsigned r[4], unsigned addr) {
    asm volatile("ldmatrix.sync.aligned.m8n8.x4.shared.b16 {%0,%1,%2,%3}, [%4];"
                 : "=r"(r[0]), "=r"(r[1]), "=r"(r[2]), "=r"(r[3]) : "r"(addr));
}
__device__ __forceinline__ void mma16816(float c[4], const unsigned a[4],
                                         unsigned b0, unsigned b1) {
    asm volatile(
        "mma.sync.aligned.m16n8k16.row.col.f32.bf16.bf16.f32 "
        "{%0,%1,%2,%3}, {%4,%5,%6,%7}, {%8,%9}, {%0,%1,%2,%3};"
        : "+f"(c[0]), "+f"(c[1]), "+f"(c[2]), "+f"(c[3])
        : "r"(a[0]), "r"(a[1]), "r"(a[2]), "r"(a[3]), "r"(b0), "r"(b1));
}
__device__ __forceinline__ void bf16split(float v, unsigned short& h,
                                          unsigned short& l) {
    __nv_bfloat16 hi = __float2bfloat16_rn(v);
    float res = v - __bfloat162float(hi);
    __nv_bfloat16 lo = __float2bfloat16_rn(res);
    h = *(unsigned short*)&hi;
    l = *(unsigned short*)&lo;
}

// ---------------------------------------------------------------------------
// K0: normalize index dtypes (int64 vs int32 delivery; detection as before).
// ---------------------------------------------------------------------------
__global__ void k_convert(const unsigned* __restrict__ xbuf,
                          const unsigned* __restrict__ eibuf) {
    unsigned odd_or = 0;
#pragma unroll
    for (int i = 0; i < 32; i++) odd_or |= eibuf[2 * i + 1];
    bool mode64 = (odd_or == 0);

    int t = blockIdx.x * blockDim.x + threadIdx.x;
    if (t < NE) {
        g_src[t] = (int)(mode64 ? eibuf[2 * t]        : eibuf[t]);
        g_dst[t] = (int)(mode64 ? eibuf[2 * (NE + t)] : eibuf[NE + t]);
    }
    if (t < NN) g_x[t] = (int)(mode64 ? xbuf[2 * t] : xbuf[t]);
}

// ---------------------------------------------------------------------------
// K1: h = emb[x];  agg1 = (1+eps)*h
// ---------------------------------------------------------------------------
__global__ void k_embed(const float4* __restrict__ emb4) {
    int t = blockIdx.x * blockDim.x + threadIdx.x;
    int node = t >> 5;
    int c    = t & 31;
    float4 v = emb4[g_x[node] * 32 + c];
    ((float4*)g_h)[t] = v;
    float4 a = make_float4(v.x * (1.f + EPSF), v.y * (1.f + EPSF),
                           v.z * (1.f + EPSF), v.w * (1.f + EPSF));
    ((float4*)g_agg1)[t] = a;
}

// ---------------------------------------------------------------------------
// K-prep: ALL weight splits in one launch.
//   t in [0, 2048):          E1w^T hi/lo  (128n x 16k)
//   t in [2048, 10240):      W1^T hi/lo   (64n x 128k)
//   t in [10240, 11264):     E2w^T hi/lo  (64n x 16k)
// ---------------------------------------------------------------------------
__global__ void k_prepall(const float* __restrict__ E1w,
                          const float* __restrict__ W1,
                          const float* __restrict__ E2w) {
    int t = blockIdx.x * blockDim.x + threadIdx.x;
    if (t < 2048) {
        int n = t >> 4, k = t & 15;
        unsigned short h, l;
        bf16split(E1w[k * EMB + n], h, l);
        g_w1hi[t] = h; g_w1lo[t] = l;
    } else if (t < 10240) {
        int u = t - 2048;
        int n = u >> 7, kk = u & 127;
        unsigned short h, l;
        bf16split(W1[kk * D1 + n], h, l);
        g_w1bh[u] = h; g_w1bl[u] = l;
    } else if (t < 11264) {
        int u = t - 10240;
        int n = u >> 4, k = u & 15;
        unsigned short h, l;
        bf16split(E2w[k * D1 + n], h, l);
        g_w2hi[u] = h; g_w2lo[u] = l;
    }
}

// ---------------------------------------------------------------------------
// K2: edge pass 1. Block = 32-edge tile. uint4 weight staging.
// ---------------------------------------------------------------------------
#define ET1  32
#define EESTRIDE 132

__global__ void __launch_bounds__(256, 6)
k_edge1(const float4* __restrict__ ea4,
        const float4* __restrict__ b4) {   // E1b as 32 float4
    __shared__ __align__(16) unsigned short sEaH[ET1][16];
    __shared__ __align__(16) unsigned short sEaL[ET1][16];
    __shared__ __align__(16) unsigned short sWtH[EMB][16];
    __shared__ __align__(16) unsigned short sWtL[EMB][16];
    __shared__ __align__(16) float sEe[ET1][EESTRIDE];

    int tid  = threadIdx.x;
    int lane = tid & 31;
    int w    = tid >> 5;
    int e0   = blockIdx.x * ET1;

    float4 bias = b4[lane];

    // Weight staging: 256 uint4 per buffer, 1 per thread.
    {
        ((uint4*)sWtH)[tid] = ((const uint4*)g_w1hi)[tid];
        ((uint4*)sWtL)[tid] = ((const uint4*)g_w1lo)[tid];
    }
    if (tid < ET1 * 4) {
        int el = tid >> 2;
        int pt = tid & 3;
        float4 v = ea4[(size_t)(e0 + el) * 4 + pt];
        unsigned short h_[4], l_[4];
        float vv[4] = {v.x, v.y, v.z, v.w};
#pragma unroll
        for (int i = 0; i < 4; i++) bf16split(vv[i], h_[i], l_[i]);
        *(uint2*)&sEaH[el][pt * 4] = *(uint2*)h_;
        *(uint2*)&sEaL[el][pt * 4] = *(uint2*)l_;
    }
    __syncthreads();

    // Phase A: warp (w>>2 -> m16 group of 2, w&3 -> 32-col quarter)
    {
        int wm = (w >> 2) * 16;
        int wn = (w & 3) * 32;
        int q  = lane >> 3;
        int li = lane & 7;
        int rowoff = (q & 1) * 8 + li;
        int coloff = (q >> 1) * 8;

        unsigned ah[4], al[4];
        ldx4(ah, (unsigned)__cvta_generic_to_shared(&sEaH[wm + rowoff][coloff]));
        ldx4(al, (unsigned)__cvta_generic_to_shared(&sEaL[wm + rowoff][coloff]));

        float acc[4][4];
#pragma unroll
        for (int n = 0; n < 4; n++)
#pragma unroll
            for (int p = 0; p < 4; p++) acc[n][p] = 0.f;

#pragma unroll
        for (int nt = 0; nt < 2; nt++) {
            unsigned bh[4], bl[4];
            ldx4(bh, (unsigned)__cvta_generic_to_shared(&sWtH[wn + nt * 16 + rowoff][coloff]));
            ldx4(bl, (unsigned)__cvta_generic_to_shared(&sWtL[wn + nt * 16 + rowoff][coloff]));
            mma16816(acc[2 * nt],     ah, bh[0], bh[2]);
            mma16816(acc[2 * nt],     ah, bl[0], bl[2]);
            mma16816(acc[2 * nt],     al, bh[0], bh[2]);
            mma16816(acc[2 * nt + 1], ah, bh[1], bh[3]);
            mma16816(acc[2 * nt + 1], ah, bl[1], bl[3]);
            mma16816(acc[2 * nt + 1], al, bh[1], bh[3]);
        }

        int g  = lane >> 2;
        int tg = lane & 3;
#pragma unroll
        for (int n = 0; n < 4; n++) {
            int col = wn + n * 8 + tg * 2;
            *(float2*)&sEe[wm + g][col]     = make_float2(acc[n][0], acc[n][1]);
            *(float2*)&sEe[wm + g + 8][col] = make_float2(acc[n][2], acc[n][3]);
        }
    }
    __syncthreads();

    // Phase B: warp per edge (8 warps x 4 iterations).
    const float4* h4 = (const float4*)g_h;
#pragma unroll
    for (int it = 0; it < ET1 / 8; it++) {
        int el = w * (ET1 / 8) + it;
        int e  = e0 + el;
        int src = g_src[e];
        int dst = g_dst[e];

        float4 ev = *(const float4*)&sEe[el][lane * 4];
        float4 hv = h4[src * 32 + lane];
        float m0 = fmaxf(hv.x + ev.x + bias.x, 0.f);
        float m1 = fmaxf(hv.y + ev.y + bias.y, 0.f);
        float m2 = fmaxf(hv.z + ev.z + bias.z, 0.f);
        float m3 = fmaxf(hv.w + ev.w + bias.w, 0.f);

        float* p = g_agg1 + (size_t)dst * EMB + lane * 4;
        asm volatile("red.global.add.v4.f32 [%0], {%1,%2,%3,%4};"
                     :: "l"(p), "f"(m0), "f"(m1), "f"(m2), "f"(m3)
                     : "memory");
    }
}

// ---------------------------------------------------------------------------
// K3: h1 = leaky_relu(agg1 @ W1 + b1); agg2 = (1+eps)*h1.  TENSORIZED
// (R11-validated). Block = 64 nodes, 8 warps (4m x 2n), K=128 in two halves.
// ---------------------------------------------------------------------------
#define L1S 72

__global__ void __launch_bounds__(256)
k_lin1(const float* __restrict__ b1) {
    __shared__ __align__(16) unsigned short sAh[64][L1S];
    __shared__ __align__(16) unsigned short sAl[64][L1S];
    __shared__ __align__(16) unsigned short sBh[64][L1S];
    __shared__ __align__(16) unsigned short sBl[64][L1S];

    int tid  = threadIdx.x;
    int lane = tid & 31;
    int w    = tid >> 5;
    int node0 = blockIdx.x * 64;

    int wm = (w >> 1) * 16;
    int wn = (w & 1) * 32;
    int q  = lane >> 3;
    int li = lane & 7;
    int rowoff = (q & 1) * 8 + li;
    int coloff = (q >> 1) * 8;
    int g  = lane >> 2;
    int tg = lane & 3;

    float acc[4][4];
#pragma unroll
    for (int n = 0; n < 4; n++) {
        int col = wn + n * 8 + tg * 2;
        float bb0 = b1[col];
        float bb1 = b1[col + 1];
        acc[n][0] = bb0; acc[n][1] = bb1;
        acc[n][2] = bb0; acc[n][3] = bb1;
    }

    const unsigned* wb_h = (const unsigned*)g_w1bh;   // [64 n][64 u32]
    const unsigned* wb_l = (const unsigned*)g_w1bl;

#pragma unroll
    for (int kh = 0; kh < 2; kh++) {
        if (kh) __syncthreads();
#pragma unroll
        for (int i = 0; i < 4; i++) {
            int lin = tid + i * 256;
            int nd  = lin >> 4;
            int c4  = lin & 15;
            float4 v = *(const float4*)&g_agg1[(size_t)(node0 + nd) * EMB + kh * 64 + c4 * 4];
            unsigned short h_[4], l_[4];
            float vv[4] = {v.x, v.y, v.z, v.w};
#pragma unroll
            for (int j = 0; j < 4; j++) bf16split(vv[j], h_[j], l_[j]);
            *(uint2*)&sAh[nd][c4 * 4] = *(uint2*)h_;
            *(uint2*)&sAl[nd][c4 * 4] = *(uint2*)l_;
        }
#pragma unroll
        for (int i = 0; i < 8; i++) {
            int lin = tid + i * 256;          // 0..2047
            int n   = lin >> 5;
            int c2  = lin & 31;
            ((unsigned*)&sBh[n][c2 * 2])[0] = wb_h[n * 64 + kh * 32 + c2];
            ((unsigned*)&sBl[n][c2 * 2])[0] = wb_l[n * 64 + kh * 32 + c2];
        }
        __syncthreads();

#pragma unroll
        for (int ks = 0; ks < 4; ks++) {
            unsigned ah[4], al[4];
            ldx4(ah, (unsigned)__cvta_generic_to_shared(&sAh[wm + rowoff][ks * 16 + coloff]));
            ldx4(al, (unsigned)__cvta_generic_to_shared(&sAl[wm + rowoff][ks * 16 + coloff]));
#pragma unroll
            for (int nt = 0; nt < 2; nt++) {
                unsigned bh[4], bl[4];
                ldx4(bh, (unsigned)__cvta_generic_to_shared(&sBh[wn + nt * 16 + rowoff][ks * 16 + coloff]));
                ldx4(bl, (unsigned)__cvta_generic_to_shared(&sBl[wn + nt * 16 + rowoff][ks * 16 + coloff]));
                mma16816(acc[2 * nt],     ah, bh[0], bh[2]);
                mma16816(acc[2 * nt],     ah, bl[0], bl[2]);
                mma16816(acc[2 * nt],     al, bh[0], bh[2]);
                mma16816(acc[2 * nt + 1], ah, bh[1], bh[3]);
                mma16816(acc[2 * nt + 1], ah, bl[1], bl[3]);
                mma16816(acc[2 * nt + 1], al, bh[1], bh[3]);
            }
        }
    }

#pragma unroll
    for (int n = 0; n < 4; n++) {
        int col = wn + n * 8 + tg * 2;
        float v0 = acc[n][0], v1 = acc[n][1], v2 = acc[n][2], v3 = acc[n][3];
        float a0 = v0 >= 0.f ? v0 : SLOPEF * v0;
        float a1 = v1 >= 0.f ? v1 : SLOPEF * v1;
        float a2 = v2 >= 0.f ? v2 : SLOPEF * v2;
        float a3 = v3 >= 0.f ? v3 : SLOPEF * v3;
        size_t r0 = (size_t)(node0 + wm + g) * D1 + col;
        size_t r1 = (size_t)(node0 + wm + g + 8) * D1 + col;
        *(float2*)&g_h1[r0]   = make_float2(a0, a1);
        *(float2*)&g_h1[r1]   = make_float2(a2, a3);
        *(float2*)&g_agg2[r0] = make_float2((1.f + EPSF) * a0, (1.f + EPSF) * a1);
        *(float2*)&g_agg2[r1] = make_float2((1.f + EPSF) * a2, (1.f + EPSF) * a3);
    }
}

// ---------------------------------------------------------------------------
// K4: edge pass 2, tensorized. Block = 64-edge tile. uint4 weight staging.
// Phase B: 2 edges per warp — half-warp (16 lanes x float4) covers the full
// 64-col h1 row: per 2 edges 1 LDG.128 + 1 red.v4 (was 2 LDG.64 + 2 red.v2).
// ---------------------------------------------------------------------------
#define ET   64
#define EESTRIDE2 68

__global__ void __launch_bounds__(256)
k_edge2(const float4* __restrict__ ea4,
        const float4* __restrict__ b2q) {  // E2b as 16 float4
    __shared__ __align__(16) unsigned short sEaH[ET][16];
    __shared__ __align__(16) unsigned short sEaL[ET][16];
    __shared__ __align__(16) unsigned short sW2H[D1][16];
    __shared__ __align__(16) unsigned short sW2L[D1][16];
    __shared__ __align__(16) float sEe[ET][EESTRIDE2];

    int tid  = threadIdx.x;
    int lane = tid & 31;
    int w    = tid >> 5;
    int e0   = blockIdx.x * ET;

    // Weight staging: 128 uint4 per buffer.
    if (tid < 128) {
        ((uint4*)sW2H)[tid] = ((const uint4*)g_w2hi)[tid];
        ((uint4*)sW2L)[tid] = ((const uint4*)g_w2lo)[tid];
    }
    {
        int el = tid >> 2;
        int pt = tid & 3;
        float4 v = ea4[(size_t)(e0 + el) * 4 + pt];
        unsigned short h_[4], l_[4];
        float vv[4] = {v.x, v.y, v.z, v.w};
#pragma unroll
        for (int i = 0; i < 4; i++) bf16split(vv[i], h_[i], l_[i]);
        *(uint2*)&sEaH[el][pt * 4] = *(uint2*)h_;
        *(uint2*)&sEaL[el][pt * 4] = *(uint2*)l_;
    }
    __syncthreads();

    {
        int wm = (w >> 1) * 16;
        int wn = (w & 1) * 32;
        int q  = lane >> 3;
        int li = lane & 7;
        int rowoff = (q & 1) * 8 + li;
        int coloff = (q >> 1) * 8;

        unsigned ah[4], al[4];
        ldx4(ah, (unsigned)__cvta_generic_to_shared(&sEaH[wm + rowoff][coloff]));
        ldx4(al, (unsigned)__cvta_generic_to_shared(&sEaL[wm + rowoff][coloff]));

        float acc[4][4];
#pragma unroll
        for (int n = 0; n < 4; n++)
#pragma unroll
            for (int p = 0; p < 4; p++) acc[n][p] = 0.f;

#pragma unroll
        for (int nt = 0; nt < 2; nt++) {
            unsigned bh[4], bl[4];
            ldx4(bh, (unsigned)__cvta_generic_to_shared(&sW2H[wn + nt * 16 + rowoff][coloff]));
            ldx4(bl, (unsigned)__cvta_generic_to_shared(&sW2L[wn + nt * 16 + rowoff][coloff]));
            mma16816(acc[2 * nt],     ah, bh[0], bh[2]);
            mma16816(acc[2 * nt],     ah, bl[0], bl[2]);
            mma16816(acc[2 * nt],     al, bh[0], bh[2]);
            mma16816(acc[2 * nt + 1], ah, bh[1], bh[3]);
            mma16816(acc[2 * nt + 1], ah, bl[1], bl[3]);
            mma16816(acc[2 * nt + 1], al, bh[1], bh[3]);
        }

        int g  = lane >> 2;
        int tg = lane & 3;
#pragma unroll
        for (int n = 0; n < 4; n++) {
            int col = wn + n * 8 + tg * 2;
            *(float2*)&sEe[wm + g][col]     = make_float2(acc[n][0], acc[n][1]);
            *(float2*)&sEe[wm + g + 8][col] = make_float2(acc[n][2], acc[n][3]);
        }
    }
    __syncthreads();

    // Phase B: 2 edges per warp per iteration. sub = which edge half,
    // cl = 4-col group (16 x 4 = 64 cols = full row).
    {
        int sub = lane >> 4;        // 0 or 1
        int cl  = lane & 15;        // 0..15
        float4 bias = b2q[cl];
        const float4* h14 = (const float4*)g_h1;   // 16 float4 per row

#pragma unroll
        for (int it = 0; it < ET / 16; it++) {     // 4 iterations
            int el = w * (ET / 8) + it * 2 + sub;
            int e  = e0 + el;
            int src = g_src[e];
            int dst = g_dst[e];

            float4 ev = *(const float4*)&sEe[el][cl * 4];
            float4 hv = h14[src * 16 + cl];
            float m0 = fmaxf(hv.x + ev.x + bias.x, 0.f);
            float m1 = fmaxf(hv.y + ev.y + bias.y, 0.f);
            float m2 = fmaxf(hv.z + ev.z + bias.z, 0.f);
            float m3 = fmaxf(hv.w + ev.w + bias.w, 0.f);

            float* p = g_agg2 + (size_t)dst * D1 + cl * 4;
            asm volatile("red.global.add.v4.f32 [%0], {%1,%2,%3,%4};"
                         :: "l"(p), "f"(m0), "f"(m1), "f"(m2), "f"(m3)
                         : "memory");
        }
    }
}

// ---------------------------------------------------------------------------
// K5: h2 = agg2 @ W2 + b2, stored as bf16 hi + bf16 lo residual.
// ---------------------------------------------------------------------------
__global__ void __launch_bounds__(256)
k_lin2(const float* __restrict__ W2, const float* __restrict__ b2) {
    __shared__ float sW[D1][D2 + 1];
    __shared__ float srow[8][D1 + 4];

    int tid  = threadIdx.x;
    int warp = tid >> 5;
    int lane = tid & 31;

    for (int i = tid; i < D1 * D2; i += 256)
        sW[i >> 5][i & 31] = W2[i];

    int n = blockIdx.x * 8 + warp;
    float2 rv = *(const float2*)(g_agg2 + (size_t)n * D1 + lane * 2);
    srow[warp][lane * 2]     = rv.x;
    srow[warp][lane * 2 + 1] = rv.y;
    __syncthreads();

    float acc = b2[lane];
#pragma unroll
    for (int k = 0; k < D1; k++)
        acc = fmaf(srow[warp][k], sW[k][lane], acc);

    unsigned short h, l;
    bf16split(acc, h, l);
    g_h2hi[(size_t)n * D2 + lane] = h;
    g_h2lo[(size_t)n * D2 + lane] = l;
}

// ---------------------------------------------------------------------------
// K6: C = h2 @ h2^T via bf16 tensor cores, uint4 staging, SYMMETRIC
// (R12-validated).
// ---------------------------------------------------------------------------
#define SROW 40

__global__ void __launch_bounds__(256)
k_gemm(float* __restrict__ C) {
    int bi = blockIdx.y;
    int bj = blockIdx.x;
    if (bj < bi) return;

    __shared__ __align__(16) unsigned short Ah[128 * SROW];
    __shared__ __align__(16) unsigned short Al[128 * SROW];
    __shared__ __align__(16) unsigned short Bh[128 * SROW];
    __shared__ __align__(16) unsigned short Bl[128 * SROW];

    int tid = threadIdx.x;

    {
        const uint4* h2h4 = (const uint4*)g_h2hi;
        const uint4* h2l4 = (const uint4*)g_h2lo;
        uint4* Ah4 = (uint4*)Ah;
        uint4* Al4 = (uint4*)Al;
        uint4* Bh4 = (uint4*)Bh;
        uint4* Bl4 = (uint4*)Bl;
#pragma unroll
        for (int i = 0; i < 2; i++) {
            int idx = tid + i * 256;       // 0..511
            int r = idx >> 2;
            int q = idx & 3;
            int sm = r * 5 + q;
            Ah4[sm] = h2h4[(size_t)(bi * 128 + r) * 4 + q];
            Al4[sm] = h2l4[(size_t)(bi * 128 + r) * 4 + q];
            Bh4[sm] = h2h4[(size_t)(bj * 128 + r) * 4 + q];
            Bl4[sm] = h2l4[(size_t)(bj * 128 + r) * 4 + q];
        }
    }
    __syncthreads();

    int w    = tid >> 5;
    int lane = tid & 31;
    int wm   = (w >> 1) * 32;
    int wn   = (w & 1) * 64;
    int q    = lane >> 3;
    int li   = lane & 7;
    int rowoff = (q & 1) * 8 + li;
    int coloff = (q >> 1) * 8;

    float acc[2][8][4];
#pragma unroll
    for (int mt = 0; mt < 2; mt++)
#pragma unroll
        for (int n = 0; n < 8; n++)
#pragma unroll
            for (int p = 0; p < 4; p++) acc[mt][n][p] = 0.f;

#pragma unroll
    for (int ks = 0; ks < 2; ks++) {
        unsigned ah[2][4], al[2][4];
#pragma unroll
        for (int mt = 0; mt < 2; mt++) {
            int off = (wm + mt * 16 + rowoff) * SROW + ks * 16 + coloff;
            ldx4(ah[mt], (unsigned)__cvta_generic_to_shared(&Ah[off]));
            ldx4(al[mt], (unsigned)__cvta_generic_to_shared(&Al[off]));
        }
#pragma unroll
        for (int nt = 0; nt < 4; nt++) {
            int off = (wn + nt * 16 + rowoff) * SROW + ks * 16 + coloff;
            unsigned bh[4], bl[4];
            ldx4(bh, (unsigned)__cvta_generic_to_shared(&Bh[off]));
            ldx4(bl, (unsigned)__cvta_generic_to_shared(&Bl[off]));
#pragma unroll
            for (int mt = 0; mt < 2; mt++) {
                mma16816(acc[mt][2 * nt],     ah[mt], bh[0], bh[2]);
                mma16816(acc[mt][2 * nt],     ah[mt], bl[0], bl[2]);
                mma16816(acc[mt][2 * nt],     al[mt], bh[0], bh[2]);
                mma16816(acc[mt][2 * nt + 1], ah[mt], bh[1], bh[3]);
                mma16816(acc[mt][2 * nt + 1], ah[mt], bl[1], bl[3]);
                mma16816(acc[mt][2 * nt + 1], al[mt], bh[1], bh[3]);
            }
        }
    }

    int g  = lane >> 2;
    int tg = lane & 3;
#pragma unroll
    for (int mt = 0; mt < 2; mt++) {
        int row0 = bi * 128 + wm + mt * 16 + g;
#pragma unroll
        for (int n = 0; n < 8; n++) {
            int col = bj * 128 + wn + n * 8 + tg * 2;
            float2* p0 = (float2*)(C + (size_t)row0 * NN + col);
            float2* p1 = (float2*)(C + (size_t)(row0 + 8) * NN + col);
            *p0 = make_float2(acc[mt][n][0], acc[mt][n][1]);
            *p1 = make_float2(acc[mt][n][2], acc[mt][n][3]);
        }
    }
    if (bi != bj) {
#pragma unroll
        for (int mt = 0; mt < 2; mt++) {
            int row0 = bi * 128 + wm + mt * 16 + g;
#pragma unroll
            for (int n = 0; n < 8; n++) {
                int col = bj * 128 + wn + n * 8 + tg * 2;
                C[(size_t)col * NN + row0]           = acc[mt][n][0];
                C[(size_t)(col + 1) * NN + row0]     = acc[mt][n][1];
                C[(size_t)col * NN + row0 + 8]       = acc[mt][n][2];
                C[(size_t)(col + 1) * NN + row0 + 8] = acc[mt][n][3];
            }
        }
    }
}

// ---------------------------------------------------------------------------
extern "C" void kernel_launch(void* const* d_in, const int* in_sizes, int n_in,
                              void* d_out, int out_size) {
    const unsigned* xbuf  = (const unsigned*)d_in[0];
    const unsigned* eibuf = (const unsigned*)d_in[1];
    const float*    ea    = (const float*)d_in[2];
    const float*    emb   = (const float*)d_in[3];
    const float*    W1    = (const float*)d_in[4];
    const float*    b1    = (const float*)d_in[5];
    const float*    E1w   = (const float*)d_in[6];
    const float*    E1b   = (const float*)d_in[7];
    const float*    W2    = (const float*)d_in[8];
    const float*    b2    = (const float*)d_in[9];
    const float*    E2w   = (const float*)d_in[10];
    const float*    E2b   = (const float*)d_in[11];
    float* out = (float*)d_out;

    k_convert<<<(NE + 255) / 256, 256>>>(xbuf, eibuf);      // idx 0
    k_embed<<<NN * 32 / 256, 256>>>((const float4*)emb);    // idx 1
    k_prepall<<<44, 256>>>(E1w, W1, E2w);                   // idx 2
    k_edge1<<<NE / ET1, 256>>>((const float4*)ea,           // idx 3 (profiled)
                               (const float4*)E1b);
    k_lin1<<<NN / 64, 256>>>(b1);
    k_edge2<<<NE / ET, 256>>>((const float4*)ea,
                              (const float4*)E2b);
    k_lin2<<<NN / 8, 256>>>(W2, b2);
    dim3 g(NN / 128, NN / 128);
    k_gemm<<<g, 256>>>(out);
}

// round 14
// speedup vs baseline: 1.3874x; 1.3874x over previous
#include <cuda_runtime.h>
#include <cuda_bf16.h>

// GINE-conv network:
//   h = emb[x]; h = leaky_relu(gine(h, E1)); h2 = gine(h, E2); out = h2 @ h2.T
// N=8192, E=262144, dims 128 -> 64 -> 32, out 8192x8192 f32.
// R14: FULL REVERT to R12 (158.7us validated). R13's uint4 edge staging and
//      2-edge-per-warp edge2 both regressed (edge1 54->75us; total +60us).

#define NN     8192
#define NE     262144
#define EMB    128
#define D1     64
#define D2     32
#define EPSF   1e-9f
#define SLOPEF 0.01f

__device__ __align__(16) float g_h[NN * EMB];
__device__ __align__(16) float g_agg1[NN * EMB];
__device__ __align__(16) float g_h1[NN * D1];
__device__ __align__(16) float g_agg2[NN * D1];
__device__ __align__(16) unsigned short g_h2hi[NN * D2];   // bf16 hi
__device__ __align__(16) unsigned short g_h2lo[NN * D2];   // bf16 lo residual
__device__ __align__(16) unsigned short g_w1hi[EMB * 16];  // E1w^T hi [n][k]
__device__ __align__(16) unsigned short g_w1lo[EMB * 16];  // E1w^T lo [n][k]
__device__ __align__(16) unsigned short g_w2hi[D1 * 16];   // E2w^T hi [n][k]
__device__ __align__(16) unsigned short g_w2lo[D1 * 16];   // E2w^T lo [n][k]
__device__ __align__(16) unsigned short g_w1bh[D1 * EMB];  // W1^T hi [n][k]
__device__ __align__(16) unsigned short g_w1bl[D1 * EMB];  // W1^T lo [n][k]
__device__ int g_x[NN];
__device__ int g_src[NE];
__device__ int g_dst[NE];

__device__ __forceinline__ void ldx4(unsigned r[4], unsigned addr) {
    asm volatile("ldmatrix.sync.aligned.m8n8.x4.shared.b16 {%0,%1,%2,%3}, [%4];"
                 : "=r"(r[0]), "=r"(r[1]), "=r"(r[2]), "=r"(r[3]) : "r"(addr));
}
__device__ __forceinline__ void mma16816(float c[4], const unsigned a[4],
                                         unsigned b0, unsigned b1) {
    asm volatile(
        "mma.sync.aligned.m16n8k16.row.col.f32.bf16.bf16.f32 "
        "{%0,%1,%2,%3}, {%4,%5,%6,%7}, {%8,%9}, {%0,%1,%2,%3};"
        : "+f"(c[0]), "+f"(c[1]), "+f"(c[2]), "+f"(c[3])
        : "r"(a[0]), "r"(a[1]), "r"(a[2]), "r"(a[3]), "r"(b0), "r"(b1));
}
__device__ __forceinline__ void bf16split(float v, unsigned short& h,
                                          unsigned short& l) {
    __nv_bfloat16 hi = __float2bfloat16_rn(v);
    float res = v - __bfloat162float(hi);
    __nv_bfloat16 lo = __float2bfloat16_rn(res);
    h = *(unsigned short*)&hi;
    l = *(unsigned short*)&lo;
}

// ---------------------------------------------------------------------------
// K0: normalize index dtypes (int64 vs int32 delivery; detection as before).
// ---------------------------------------------------------------------------
__global__ void k_convert(const unsigned* __restrict__ xbuf,
                          const unsigned* __restrict__ eibuf) {
    unsigned odd_or = 0;
#pragma unroll
    for (int i = 0; i < 32; i++) odd_or |= eibuf[2 * i + 1];
    bool mode64 = (odd_or == 0);

    int t = blockIdx.x * blockDim.x + threadIdx.x;
    if (t < NE) {
        g_src[t] = (int)(mode64 ? eibuf[2 * t]        : eibuf[t]);
        g_dst[t] = (int)(mode64 ? eibuf[2 * (NE + t)] : eibuf[NE + t]);
    }
    if (t < NN) g_x[t] = (int)(mode64 ? xbuf[2 * t] : xbuf[t]);
}

// ---------------------------------------------------------------------------
// K1: h = emb[x];  agg1 = (1+eps)*h
// ---------------------------------------------------------------------------
__global__ void k_embed(const float4* __restrict__ emb4) {
    int t = blockIdx.x * blockDim.x + threadIdx.x;
    int node = t >> 5;
    int c    = t & 31;
    float4 v = emb4[g_x[node] * 32 + c];
    ((float4*)g_h)[t] = v;
    float4 a = make_float4(v.x * (1.f + EPSF), v.y * (1.f + EPSF),
                           v.z * (1.f + EPSF), v.w * (1.f + EPSF));
    ((float4*)g_agg1)[t] = a;
}

// ---------------------------------------------------------------------------
// Weight prep kernels (bf16 hi/lo transposed splits).
// ---------------------------------------------------------------------------
__global__ void k_prepw(const float* __restrict__ E1w) {
    int t = blockIdx.x * blockDim.x + threadIdx.x;   // 0..2047
    int n = t >> 4;
    int k = t & 15;
    unsigned short h, l;
    bf16split(E1w[k * EMB + n], h, l);
    g_w1hi[t] = h;
    g_w1lo[t] = l;
}

__global__ void k_prepw2(const float* __restrict__ E2w) {
    int t = blockIdx.x * blockDim.x + threadIdx.x;   // 0..1023
    int n = t >> 4;
    int k = t & 15;
    unsigned short h, l;
    bf16split(E2w[k * D1 + n], h, l);
    g_w2hi[t] = h;
    g_w2lo[t] = l;
}

// W1 [128 k][64 n] -> W1^T hi/lo [64 n][128 k]
__global__ void k_prepw1(const float* __restrict__ W1) {
    int t = blockIdx.x * blockDim.x + threadIdx.x;   // 0..8191
    int n = t >> 7;
    int kk = t & 127;
    unsigned short h, l;
    bf16split(W1[kk * D1 + n], h, l);
    g_w1bh[t] = h;
    g_w1bl[t] = l;
}

// ---------------------------------------------------------------------------
// K2: edge pass 1. Block = 32-edge tile.
// Phase A: ee[32][128] = ea_tile @ E1w via bf16 hi/lo mma -> smem.
// Phase B: warp per edge (4 iter): m = relu(h[src]+ee+b); red.v4 agg1[dst].
// ---------------------------------------------------------------------------
#define ET1  32
#define EESTRIDE 132

__global__ void __launch_bounds__(256, 6)
k_edge1(const float4* __restrict__ ea4,
        const float4* __restrict__ b4) {   // E1b as 32 float4
    __shared__ __align__(16) unsigned short sEaH[ET1][16];
    __shared__ __align__(16) unsigned short sEaL[ET1][16];
    __shared__ __align__(16) unsigned short sWtH[EMB][16];
    __shared__ __align__(16) unsigned short sWtL[EMB][16];
    __shared__ __align__(16) float sEe[ET1][EESTRIDE];

    int tid  = threadIdx.x;
    int lane = tid & 31;
    int w    = tid >> 5;
    int e0   = blockIdx.x * ET1;

    float4 bias = b4[lane];

    {
        const unsigned* wh = (const unsigned*)g_w1hi;
        const unsigned* wl = (const unsigned*)g_w1lo;
        unsigned* dh = (unsigned*)sWtH;
        unsigned* dl = (unsigned*)sWtL;
        for (int i = tid; i < EMB * 8; i += 256) { dh[i] = wh[i]; dl[i] = wl[i]; }
    }
    if (tid < ET1 * 4) {
        int el = tid >> 2;
        int pt = tid & 3;
        float4 v = ea4[(size_t)(e0 + el) * 4 + pt];
        unsigned short h_[4], l_[4];
        float vv[4] = {v.x, v.y, v.z, v.w};
#pragma unroll
        for (int i = 0; i < 4; i++) bf16split(vv[i], h_[i], l_[i]);
        *(uint2*)&sEaH[el][pt * 4] = *(uint2*)h_;
        *(uint2*)&sEaL[el][pt * 4] = *(uint2*)l_;
    }
    __syncthreads();

    // Phase A: warp (w>>2 -> m16 group of 2, w&3 -> 32-col quarter)
    {
        int wm = (w >> 2) * 16;
        int wn = (w & 3) * 32;
        int q  = lane >> 3;
        int li = lane & 7;
        int rowoff = (q & 1) * 8 + li;
        int coloff = (q >> 1) * 8;

        unsigned ah[4], al[4];
        ldx4(ah, (unsigned)__cvta_generic_to_shared(&sEaH[wm + rowoff][coloff]));
        ldx4(al, (unsigned)__cvta_generic_to_shared(&sEaL[wm + rowoff][coloff]));

        float acc[4][4];
#pragma unroll
        for (int n = 0; n < 4; n++)
#pragma unroll
            for (int p = 0; p < 4; p++) acc[n][p] = 0.f;

#pragma unroll
        for (int nt = 0; nt < 2; nt++) {
            unsigned bh[4], bl[4];
            ldx4(bh, (unsigned)__cvta_generic_to_shared(&sWtH[wn + nt * 16 + rowoff][coloff]));
            ldx4(bl, (unsigned)__cvta_generic_to_shared(&sWtL[wn + nt * 16 + rowoff][coloff]));
            mma16816(acc[2 * nt],     ah, bh[0], bh[2]);
            mma16816(acc[2 * nt],     ah, bl[0], bl[2]);
            mma16816(acc[2 * nt],     al, bh[0], bh[2]);
            mma16816(acc[2 * nt + 1], ah, bh[1], bh[3]);
            mma16816(acc[2 * nt + 1], ah, bl[1], bl[3]);
            mma16816(acc[2 * nt + 1], al, bh[1], bh[3]);
        }

        int g  = lane >> 2;
        int tg = lane & 3;
#pragma unroll
        for (int n = 0; n < 4; n++) {
            int col = wn + n * 8 + tg * 2;
            *(float2*)&sEe[wm + g][col]     = make_float2(acc[n][0], acc[n][1]);
            *(float2*)&sEe[wm + g + 8][col] = make_float2(acc[n][2], acc[n][3]);
        }
    }
    __syncthreads();

    // Phase B: warp per edge (8 warps x 4 iterations).
    const float4* h4 = (const float4*)g_h;
#pragma unroll
    for (int it = 0; it < ET1 / 8; it++) {
        int el = w * (ET1 / 8) + it;
        int e  = e0 + el;
        int src = g_src[e];
        int dst = g_dst[e];

        float4 ev = *(const float4*)&sEe[el][lane * 4];
        float4 hv = h4[src * 32 + lane];
        float m0 = fmaxf(hv.x + ev.x + bias.x, 0.f);
        float m1 = fmaxf(hv.y + ev.y + bias.y, 0.f);
        float m2 = fmaxf(hv.z + ev.z + bias.z, 0.f);
        float m3 = fmaxf(hv.w + ev.w + bias.w, 0.f);

        float* p = g_agg1 + (size_t)dst * EMB + lane * 4;
        asm volatile("red.global.add.v4.f32 [%0], {%1,%2,%3,%4};"
                     :: "l"(p), "f"(m0), "f"(m1), "f"(m2), "f"(m3)
                     : "memory");
    }
}

// ---------------------------------------------------------------------------
// K3: h1 = leaky_relu(agg1 @ W1 + b1); agg2 = (1+eps)*h1.  TENSORIZED
// (R11-validated). Block = 64 nodes, 8 warps (4m x 2n), K=128 in two halves.
// ---------------------------------------------------------------------------
#define L1S 72

__global__ void __launch_bounds__(256)
k_lin1(const float* __restrict__ b1) {
    __shared__ __align__(16) unsigned short sAh[64][L1S];
    __shared__ __align__(16) unsigned short sAl[64][L1S];
    __shared__ __align__(16) unsigned short sBh[64][L1S];
    __shared__ __align__(16) unsigned short sBl[64][L1S];

    int tid  = threadIdx.x;
    int lane = tid & 31;
    int w    = tid >> 5;
    int node0 = blockIdx.x * 64;

    int wm = (w >> 1) * 16;
    int wn = (w & 1) * 32;
    int q  = lane >> 3;
    int li = lane & 7;
    int rowoff = (q & 1) * 8 + li;
    int coloff = (q >> 1) * 8;
    int g  = lane >> 2;
    int tg = lane & 3;

    float acc[4][4];
#pragma unroll
    for (int n = 0; n < 4; n++) {
        int col = wn + n * 8 + tg * 2;
        float bb0 = b1[col];
        float bb1 = b1[col + 1];
        acc[n][0] = bb0; acc[n][1] = bb1;
        acc[n][2] = bb0; acc[n][3] = bb1;
    }

    const unsigned* wb_h = (const unsigned*)g_w1bh;   // [64 n][64 u32]
    const unsigned* wb_l = (const unsigned*)g_w1bl;

#pragma unroll
    for (int kh = 0; kh < 2; kh++) {
        if (kh) __syncthreads();
#pragma unroll
        for (int i = 0; i < 4; i++) {
            int lin = tid + i * 256;
            int nd  = lin >> 4;
            int c4  = lin & 15;
            float4 v = *(const float4*)&g_agg1[(size_t)(node0 + nd) * EMB + kh * 64 + c4 * 4];
            unsigned short h_[4], l_[4];
            float vv[4] = {v.x, v.y, v.z, v.w};
#pragma unroll
            for (int j = 0; j < 4; j++) bf16split(vv[j], h_[j], l_[j]);
            *(uint2*)&sAh[nd][c4 * 4] = *(uint2*)h_;
            *(uint2*)&sAl[nd][c4 * 4] = *(uint2*)l_;
        }
#pragma unroll
        for (int i = 0; i < 8; i++) {
            int lin = tid + i * 256;          // 0..2047
            int n   = lin >> 5;
            int c2  = lin & 31;
            ((unsigned*)&sBh[n][c2 * 2])[0] = wb_h[n * 64 + kh * 32 + c2];
            ((unsigned*)&sBl[n][c2 * 2])[0] = wb_l[n * 64 + kh * 32 + c2];
        }
        __syncthreads();

#pragma unroll
        for (int ks = 0; ks < 4; ks++) {
            unsigned ah[4], al[4];
            ldx4(ah, (unsigned)__cvta_generic_to_shared(&sAh[wm + rowoff][ks * 16 + coloff]));
            ldx4(al, (unsigned)__cvta_generic_to_shared(&sAl[wm + rowoff][ks * 16 + coloff]));
#pragma unroll
            for (int nt = 0; nt < 2; nt++) {
                unsigned bh[4], bl[4];
                ldx4(bh, (unsigned)__cvta_generic_to_shared(&sBh[wn + nt * 16 + rowoff][ks * 16 + coloff]));
                ldx4(bl, (unsigned)__cvta_generic_to_shared(&sBl[wn + nt * 16 + rowoff][ks * 16 + coloff]));
                mma16816(acc[2 * nt],     ah, bh[0], bh[2]);
                mma16816(acc[2 * nt],     ah, bl[0], bl[2]);
                mma16816(acc[2 * nt],     al, bh[0], bh[2]);
                mma16816(acc[2 * nt + 1], ah, bh[1], bh[3]);
                mma16816(acc[2 * nt + 1], ah, bl[1], bl[3]);
                mma16816(acc[2 * nt + 1], al, bh[1], bh[3]);
            }
        }
    }

#pragma unroll
    for (int n = 0; n < 4; n++) {
        int col = wn + n * 8 + tg * 2;
        float v0 = acc[n][0], v1 = acc[n][1], v2 = acc[n][2], v3 = acc[n][3];
        float a0 = v0 >= 0.f ? v0 : SLOPEF * v0;
        float a1 = v1 >= 0.f ? v1 : SLOPEF * v1;
        float a2 = v2 >= 0.f ? v2 : SLOPEF * v2;
        float a3 = v3 >= 0.f ? v3 : SLOPEF * v3;
        size_t r0 = (size_t)(node0 + wm + g) * D1 + col;
        size_t r1 = (size_t)(node0 + wm + g + 8) * D1 + col;
        *(float2*)&g_h1[r0]   = make_float2(a0, a1);
        *(float2*)&g_h1[r1]   = make_float2(a2, a3);
        *(float2*)&g_agg2[r0] = make_float2((1.f + EPSF) * a0, (1.f + EPSF) * a1);
        *(float2*)&g_agg2[r1] = make_float2((1.f + EPSF) * a2, (1.f + EPSF) * a3);
    }
}

// ---------------------------------------------------------------------------
// K4: edge pass 2, tensorized (R8-validated). Block = 64-edge tile.
// ---------------------------------------------------------------------------
#define ET   64
#define EESTRIDE2 68

__global__ void __launch_bounds__(256)
k_edge2(const float4* __restrict__ ea4,
        const float2* __restrict__ b2v) {  // E2b as 32 float2
    __shared__ __align__(16) unsigned short sEaH[ET][16];
    __shared__ __align__(16) unsigned short sEaL[ET][16];
    __shared__ __align__(16) unsigned short sW2H[D1][16];
    __shared__ __align__(16) unsigned short sW2L[D1][16];
    __shared__ __align__(16) float sEe[ET][EESTRIDE2];

    int tid  = threadIdx.x;
    int lane = tid & 31;
    int w    = tid >> 5;
    int e0   = blockIdx.x * ET;

    float2 bias = b2v[lane];

    {
        const unsigned* wh = (const unsigned*)g_w2hi;
        const unsigned* wl = (const unsigned*)g_w2lo;
        unsigned* dh = (unsigned*)sW2H;
        unsigned* dl = (unsigned*)sW2L;
        for (int i = tid; i < D1 * 8; i += 256) { dh[i] = wh[i]; dl[i] = wl[i]; }
    }
    {
        int el = tid >> 2;
        int pt = tid & 3;
        float4 v = ea4[(size_t)(e0 + el) * 4 + pt];
        unsigned short h_[4], l_[4];
        float vv[4] = {v.x, v.y, v.z, v.w};
#pragma unroll
        for (int i = 0; i < 4; i++) bf16split(vv[i], h_[i], l_[i]);
        *(uint2*)&sEaH[el][pt * 4] = *(uint2*)h_;
        *(uint2*)&sEaL[el][pt * 4] = *(uint2*)l_;
    }
    __syncthreads();

    {
        int wm = (w >> 1) * 16;
        int wn = (w & 1) * 32;
        int q  = lane >> 3;
        int li = lane & 7;
        int rowoff = (q & 1) * 8 + li;
        int coloff = (q >> 1) * 8;

        unsigned ah[4], al[4];
        ldx4(ah, (unsigned)__cvta_generic_to_shared(&sEaH[wm + rowoff][coloff]));
        ldx4(al, (unsigned)__cvta_generic_to_shared(&sEaL[wm + rowoff][coloff]));

        float acc[4][4];
#pragma unroll
        for (int n = 0; n < 4; n++)
#pragma unroll
            for (int p = 0; p < 4; p++) acc[n][p] = 0.f;

#pragma unroll
        for (int nt = 0; nt < 2; nt++) {
            unsigned bh[4], bl[4];
            ldx4(bh, (unsigned)__cvta_generic_to_shared(&sW2H[wn + nt * 16 + rowoff][coloff]));
            ldx4(bl, (unsigned)__cvta_generic_to_shared(&sW2L[wn + nt * 16 + rowoff][coloff]));
            mma16816(acc[2 * nt],     ah, bh[0], bh[2]);
            mma16816(acc[2 * nt],     ah, bl[0], bl[2]);
            mma16816(acc[2 * nt],     al, bh[0], bh[2]);
            mma16816(acc[2 * nt + 1], ah, bh[1], bh[3]);
            mma16816(acc[2 * nt + 1], ah, bl[1], bl[3]);
            mma16816(acc[2 * nt + 1], al, bh[1], bh[3]);
        }

        int g  = lane >> 2;
        int tg = lane & 3;
#pragma unroll
        for (int n = 0; n < 4; n++) {
            int col = wn + n * 8 + tg * 2;
            *(float2*)&sEe[wm + g][col]     = make_float2(acc[n][0], acc[n][1]);
            *(float2*)&sEe[wm + g + 8][col] = make_float2(acc[n][2], acc[n][3]);
        }
    }
    __syncthreads();

    const float2* h2v = (const float2*)g_h1;
#pragma unroll
    for (int it = 0; it < ET / 8; it++) {
        int el = w * (ET / 8) + it;
        int e  = e0 + el;
        int src = g_src[e];
        int dst = g_dst[e];

        float2 ev = *(const float2*)&sEe[el][lane * 2];
        float2 hv = h2v[src * 32 + lane];
        float m0 = fmaxf(hv.x + ev.x + bias.x, 0.f);
        float m1 = fmaxf(hv.y + ev.y + bias.y, 0.f);

        float* p = g_agg2 + (size_t)dst * D1 + lane * 2;
        asm volatile("red.global.add.v2.f32 [%0], {%1,%2};"
                     :: "l"(p), "f"(m0), "f"(m1)
                     : "memory");
    }
}

// ---------------------------------------------------------------------------
// K5: h2 = agg2 @ W2 + b2, stored as bf16 hi + bf16 lo residual.
// ---------------------------------------------------------------------------
__global__ void __launch_bounds__(256)
k_lin2(const float* __restrict__ W2, const float* __restrict__ b2) {
    __shared__ float sW[D1][D2 + 1];
    __shared__ float srow[8][D1 + 4];

    int tid  = threadIdx.x;
    int warp = tid >> 5;
    int lane = tid & 31;

    for (int i = tid; i < D1 * D2; i += 256)
        sW[i >> 5][i & 31] = W2[i];

    int n = blockIdx.x * 8 + warp;
    float2 rv = *(const float2*)(g_agg2 + (size_t)n * D1 + lane * 2);
    srow[warp][lane * 2]     = rv.x;
    srow[warp][lane * 2 + 1] = rv.y;
    __syncthreads();

    float acc = b2[lane];
#pragma unroll
    for (int k = 0; k < D1; k++)
        acc = fmaf(srow[warp][k], sW[k][lane], acc);

    unsigned short h, l;
    bf16split(acc, h, l);
    g_h2hi[(size_t)n * D2 + lane] = h;
    g_h2lo[(size_t)n * D2 + lane] = l;
}

// ---------------------------------------------------------------------------
// K6: C = h2 @ h2^T via bf16 tensor cores, uint4 staging. SYMMETRIC:
// compute bj >= bi tiles only; off-diagonal tiles also write the transpose.
// ---------------------------------------------------------------------------
#define SROW 40

__global__ void __launch_bounds__(256)
k_gemm(float* __restrict__ C) {
    int bi = blockIdx.y;
    int bj = blockIdx.x;
    if (bj < bi) return;

    __shared__ __align__(16) unsigned short Ah[128 * SROW];
    __shared__ __align__(16) unsigned short Al[128 * SROW];
    __shared__ __align__(16) unsigned short Bh[128 * SROW];
    __shared__ __align__(16) unsigned short Bl[128 * SROW];

    int tid = threadIdx.x;

    {
        const uint4* h2h4 = (const uint4*)g_h2hi;
        const uint4* h2l4 = (const uint4*)g_h2lo;
        uint4* Ah4 = (uint4*)Ah;
        uint4* Al4 = (uint4*)Al;
        uint4* Bh4 = (uint4*)Bh;
        uint4* Bl4 = (uint4*)Bl;
#pragma unroll
        for (int i = 0; i < 2; i++) {
            int idx = tid + i * 256;       // 0..511
            int r = idx >> 2;
            int q = idx & 3;
            int sm = r * 5 + q;
            Ah4[sm] = h2h4[(size_t)(bi * 128 + r) * 4 + q];
            Al4[sm] = h2l4[(size_t)(bi * 128 + r) * 4 + q];
            Bh4[sm] = h2h4[(size_t)(bj * 128 + r) * 4 + q];
            Bl4[sm] = h2l4[(size_t)(bj * 128 + r) * 4 + q];
        }
    }
    __syncthreads();

    int w    = tid >> 5;
    int lane = tid & 31;
    int wm   = (w >> 1) * 32;
    int wn   = (w & 1) * 64;
    int q    = lane >> 3;
    int li   = lane & 7;
    int rowoff = (q & 1) * 8 + li;
    int coloff = (q >> 1) * 8;

    float acc[2][8][4];
#pragma unroll
    for (int mt = 0; mt < 2; mt++)
#pragma unroll
        for (int n = 0; n < 8; n++)
#pragma unroll
            for (int p = 0; p < 4; p++) acc[mt][n][p] = 0.f;

#pragma unroll
    for (int ks = 0; ks < 2; ks++) {
        unsigned ah[2][4], al[2][4];
#pragma unroll
        for (int mt = 0; mt < 2; mt++) {
            int off = (wm + mt * 16 + rowoff) * SROW + ks * 16 + coloff;
            ldx4(ah[mt], (unsigned)__cvta_generic_to_shared(&Ah[off]));
            ldx4(al[mt], (unsigned)__cvta_generic_to_shared(&Al[off]));
        }
#pragma unroll
        for (int nt = 0; nt < 4; nt++) {
            int off = (wn + nt * 16 + rowoff) * SROW + ks * 16 + coloff;
            unsigned bh[4], bl[4];
            ldx4(bh, (unsigned)__cvta_generic_to_shared(&Bh[off]));
            ldx4(bl, (unsigned)__cvta_generic_to_shared(&Bl[off]));
#pragma unroll
            for (int mt = 0; mt < 2; mt++) {
                mma16816(acc[mt][2 * nt],     ah[mt], bh[0], bh[2]);
                mma16816(acc[mt][2 * nt],     ah[mt], bl[0], bl[2]);
                mma16816(acc[mt][2 * nt],     al[mt], bh[0], bh[2]);
                mma16816(acc[mt][2 * nt + 1], ah[mt], bh[1], bh[3]);
                mma16816(acc[mt][2 * nt + 1], ah[mt], bl[1], bl[3]);
                mma16816(acc[mt][2 * nt + 1], al[mt], bh[1], bh[3]);
            }
        }
    }

    int g  = lane >> 2;
    int tg = lane & 3;
#pragma unroll
    for (int mt = 0; mt < 2; mt++) {
        int row0 = bi * 128 + wm + mt * 16 + g;
#pragma unroll
        for (int n = 0; n < 8; n++) {
            int col = bj * 128 + wn + n * 8 + tg * 2;
            float2* p0 = (float2*)(C + (size_t)row0 * NN + col);
            float2* p1 = (float2*)(C + (size_t)(row0 + 8) * NN + col);
            *p0 = make_float2(acc[mt][n][0], acc[mt][n][1]);
            *p1 = make_float2(acc[mt][n][2], acc[mt][n][3]);
        }
    }
    if (bi != bj) {
        // Mirror: C[col][row] = C[row][col]. For fixed tg, 8 consecutive g
        // lanes write 8 consecutive rows -> 32B contiguous per STG.32 group.
#pragma unroll
        for (int mt = 0; mt < 2; mt++) {
            int row0 = bi * 128 + wm + mt * 16 + g;
#pragma unroll
            for (int n = 0; n < 8; n++) {
                int col = bj * 128 + wn + n * 8 + tg * 2;
                C[(size_t)col * NN + row0]           = acc[mt][n][0];
                C[(size_t)(col + 1) * NN + row0]     = acc[mt][n][1];
                C[(size_t)col * NN + row0 + 8]       = acc[mt][n][2];
                C[(size_t)(col + 1) * NN + row0 + 8] = acc[mt][n][3];
            }
        }
    }
}

// ---------------------------------------------------------------------------
extern "C" void kernel_launch(void* const* d_in, const int* in_sizes, int n_in,
                              void* d_out, int out_size) {
    const unsigned* xbuf  = (const unsigned*)d_in[0];
    const unsigned* eibuf = (const unsigned*)d_in[1];
    const float*    ea    = (const float*)d_in[2];
    const float*    emb   = (const float*)d_in[3];
    const float*    W1    = (const float*)d_in[4];
    const float*    b1    = (const float*)d_in[5];
    const float*    E1w   = (const float*)d_in[6];
    const float*    E1b   = (const float*)d_in[7];
    const float*    W2    = (const float*)d_in[8];
    const float*    b2    = (const float*)d_in[9];
    const float*    E2w   = (const float*)d_in[10];
    const float*    E2b   = (const float*)d_in[11];
    float* out = (float*)d_out;

    k_convert<<<(NE + 255) / 256, 256>>>(xbuf, eibuf);      // idx 0
    k_embed<<<NN * 32 / 256, 256>>>((const float4*)emb);    // idx 1
    k_prepw<<<8, 256>>>(E1w);                               // idx 2
    k_edge1<<<NE / ET1, 256>>>((const float4*)ea,           // idx 3 (profiled)
                               (const float4*)E1b);
    k_prepw1<<<32, 256>>>(W1);
    k_lin1<<<NN / 64, 256>>>(b1);
    k_prepw2<<<4, 256>>>(E2w);
    k_edge2<<<NE / ET, 256>>>((const float4*)ea,
                              (const float2*)E2b);
    k_lin2<<<NN / 8, 256>>>(W2, b2);
    dim3 g(NN / 128, NN / 128);
    k_gemm<<<g, 256>>>(out);
}

// round 15
// speedup vs baseline: 1.3897x; 1.0016x over previous
#include <cuda_runtime.h>
#include <cuda_bf16.h>

// GINE-conv network:
//   h = emb[x]; h = leaky_relu(gine(h, E1)); h2 = gine(h, E2); out = h2 @ h2.T
// N=8192, E=262144, dims 128 -> 64 -> 32, out 8192x8192 f32.
// R15 vs R14 (158.0us): PERSISTENT edge kernels — 888 blocks grid-stride over
// edge tiles, staging the weight tile ONCE per block instead of per tile
// (removes ~117MB redundant L2->SMEM traffic + ~1/3 of per-block LSU issue).
// Tile inner code byte-identical to the validated R12/R14 version.

#define NN     8192
#define NE     262144
#define EMB    128
#define D1     64
#define D2     32
#define EPSF   1e-9f
#define SLOPEF 0.01f

#define PBLOCKS 888   // 148 SMs x 6 resident blocks

__device__ __align__(16) float g_h[NN * EMB];
__device__ __align__(16) float g_agg1[NN * EMB];
__device__ __align__(16) float g_h1[NN * D1];
__device__ __align__(16) float g_agg2[NN * D1];
__device__ __align__(16) unsigned short g_h2hi[NN * D2];   // bf16 hi
__device__ __align__(16) unsigned short g_h2lo[NN * D2];   // bf16 lo residual
__device__ __align__(16) unsigned short g_w1hi[EMB * 16];  // E1w^T hi [n][k]
__device__ __align__(16) unsigned short g_w1lo[EMB * 16];  // E1w^T lo [n][k]
__device__ __align__(16) unsigned short g_w2hi[D1 * 16];   // E2w^T hi [n][k]
__device__ __align__(16) unsigned short g_w2lo[D1 * 16];   // E2w^T lo [n][k]
__device__ __align__(16) unsigned short g_w1bh[D1 * EMB];  // W1^T hi [n][k]
__device__ __align__(16) unsigned short g_w1bl[D1 * EMB];  // W1^T lo [n][k]
__device__ int g_x[NN];
__device__ int g_src[NE];
__device__ int g_dst[NE];

__device__ __forceinline__ void ldx4(unsigned r[4], unsigned addr) {
    asm volatile("ldmatrix.sync.aligned.m8n8.x4.shared.b16 {%0,%1,%2,%3}, [%4];"
                 : "=r"(r[0]), "=r"(r[1]), "=r"(r[2]), "=r"(r[3]) : "r"(addr));
}
__device__ __forceinline__ void mma16816(float c[4], const unsigned a[4],
                                         unsigned b0, unsigned b1) {
    asm volatile(
        "mma.sync.aligned.m16n8k16.row.col.f32.bf16.bf16.f32 "
        "{%0,%1,%2,%3}, {%4,%5,%6,%7}, {%8,%9}, {%0,%1,%2,%3};"
        : "+f"(c[0]), "+f"(c[1]), "+f"(c[2]), "+f"(c[3])
        : "r"(a[0]), "r"(a[1]), "r"(a[2]), "r"(a[3]), "r"(b0), "r"(b1));
}
__device__ __forceinline__ void bf16split(float v, unsigned short& h,
                                          unsigned short& l) {
    __nv_bfloat16 hi = __float2bfloat16_rn(v);
    float res = v - __bfloat162float(hi);
    __nv_bfloat16 lo = __float2bfloat16_rn(res);
    h = *(unsigned short*)&hi;
    l = *(unsigned short*)&lo;
}

// ---------------------------------------------------------------------------
// K0: normalize index dtypes (int64 vs int32 delivery; detection as before).
// ---------------------------------------------------------------------------
__global__ void k_convert(const unsigned* __restrict__ xbuf,
                          const unsigned* __restrict__ eibuf) {
    unsigned odd_or = 0;
#pragma unroll
    for (int i = 0; i < 32; i++) odd_or |= eibuf[2 * i + 1];
    bool mode64 = (odd_or == 0);

    int t = blockIdx.x * blockDim.x + threadIdx.x;
    if (t < NE) {
        g_src[t] = (int)(mode64 ? eibuf[2 * t]        : eibuf[t]);
        g_dst[t] = (int)(mode64 ? eibuf[2 * (NE + t)] : eibuf[NE + t]);
    }
    if (t < NN) g_x[t] = (int)(mode64 ? xbuf[2 * t] : xbuf[t]);
}

// ---------------------------------------------------------------------------
// K1: h = emb[x];  agg1 = (1+eps)*h
// ---------------------------------------------------------------------------
__global__ void k_embed(const float4* __restrict__ emb4) {
    int t = blockIdx.x * blockDim.x + threadIdx.x;
    int node = t >> 5;
    int c    = t & 31;
    float4 v = emb4[g_x[node] * 32 + c];
    ((float4*)g_h)[t] = v;
    float4 a = make_float4(v.x * (1.f + EPSF), v.y * (1.f + EPSF),
                           v.z * (1.f + EPSF), v.w * (1.f + EPSF));
    ((float4*)g_agg1)[t] = a;
}

// ---------------------------------------------------------------------------
// Weight prep kernels (bf16 hi/lo transposed splits).
// ---------------------------------------------------------------------------
__global__ void k_prepw(const float* __restrict__ E1w) {
    int t = blockIdx.x * blockDim.x + threadIdx.x;   // 0..2047
    int n = t >> 4;
    int k = t & 15;
    unsigned short h, l;
    bf16split(E1w[k * EMB + n], h, l);
    g_w1hi[t] = h;
    g_w1lo[t] = l;
}

__global__ void k_prepw2(const float* __restrict__ E2w) {
    int t = blockIdx.x * blockDim.x + threadIdx.x;   // 0..1023
    int n = t >> 4;
    int k = t & 15;
    unsigned short h, l;
    bf16split(E2w[k * D1 + n], h, l);
    g_w2hi[t] = h;
    g_w2lo[t] = l;
}

// W1 [128 k][64 n] -> W1^T hi/lo [64 n][128 k]
__global__ void k_prepw1(const float* __restrict__ W1) {
    int t = blockIdx.x * blockDim.x + threadIdx.x;   // 0..8191
    int n = t >> 7;
    int kk = t & 127;
    unsigned short h, l;
    bf16split(W1[kk * D1 + n], h, l);
    g_w1bh[t] = h;
    g_w1bl[t] = l;
}

// ---------------------------------------------------------------------------
// K2: edge pass 1, PERSISTENT. 888 blocks grid-stride over 32-edge tiles.
// Weights staged once per block. Per tile: stage ea -> Phase A (mma) ->
// Phase B (gather + relu + red.v4). Inner code identical to R12.
// ---------------------------------------------------------------------------
#define ET1  32
#define EESTRIDE 132

__global__ void __launch_bounds__(256, 6)
k_edge1(const float4* __restrict__ ea4,
        const float4* __restrict__ b4) {   // E1b as 32 float4
    __shared__ __align__(16) unsigned short sEaH[ET1][16];
    __shared__ __align__(16) unsigned short sEaL[ET1][16];
    __shared__ __align__(16) unsigned short sWtH[EMB][16];
    __shared__ __align__(16) unsigned short sWtL[EMB][16];
    __shared__ __align__(16) float sEe[ET1][EESTRIDE];

    int tid  = threadIdx.x;
    int lane = tid & 31;
    int w    = tid >> 5;

    float4 bias = b4[lane];

    // Stage weights ONCE per persistent block.
    {
        const unsigned* wh = (const unsigned*)g_w1hi;
        const unsigned* wl = (const unsigned*)g_w1lo;
        unsigned* dh = (unsigned*)sWtH;
        unsigned* dl = (unsigned*)sWtL;
        for (int i = tid; i < EMB * 8; i += 256) { dh[i] = wh[i]; dl[i] = wl[i]; }
    }

    // Precompute per-thread constants used in phases.
    int wm1 = (w >> 2) * 16;
    int wn1 = (w & 3) * 32;
    int q   = lane >> 3;
    int li  = lane & 7;
    int rowoff = (q & 1) * 8 + li;
    int coloff = (q >> 1) * 8;
    int gg  = lane >> 2;
    int tg  = lane & 3;

    const float4* h4 = (const float4*)g_h;

    for (int tile = blockIdx.x; tile < NE / ET1; tile += PBLOCKS) {
        int e0 = tile * ET1;

        // Stage edge_attr tile (+ bf16 split).
        if (tid < ET1 * 4) {
            int el = tid >> 2;
            int pt = tid & 3;
            float4 v = ea4[(size_t)(e0 + el) * 4 + pt];
            unsigned short h_[4], l_[4];
            float vv[4] = {v.x, v.y, v.z, v.w};
#pragma unroll
            for (int i = 0; i < 4; i++) bf16split(vv[i], h_[i], l_[i]);
            *(uint2*)&sEaH[el][pt * 4] = *(uint2*)h_;
            *(uint2*)&sEaL[el][pt * 4] = *(uint2*)l_;
        }
        __syncthreads();

        // Phase A
        {
            unsigned ah[4], al[4];
            ldx4(ah, (unsigned)__cvta_generic_to_shared(&sEaH[wm1 + rowoff][coloff]));
            ldx4(al, (unsigned)__cvta_generic_to_shared(&sEaL[wm1 + rowoff][coloff]));

            float acc[4][4];
#pragma unroll
            for (int n = 0; n < 4; n++)
#pragma unroll
                for (int p = 0; p < 4; p++) acc[n][p] = 0.f;

#pragma unroll
            for (int nt = 0; nt < 2; nt++) {
                unsigned bh[4], bl[4];
                ldx4(bh, (unsigned)__cvta_generic_to_shared(&sWtH[wn1 + nt * 16 + rowoff][coloff]));
                ldx4(bl, (unsigned)__cvta_generic_to_shared(&sWtL[wn1 + nt * 16 + rowoff][coloff]));
                mma16816(acc[2 * nt],     ah, bh[0], bh[2]);
                mma16816(acc[2 * nt],     ah, bl[0], bl[2]);
                mma16816(acc[2 * nt],     al, bh[0], bh[2]);
                mma16816(acc[2 * nt + 1], ah, bh[1], bh[3]);
                mma16816(acc[2 * nt + 1], ah, bl[1], bl[3]);
                mma16816(acc[2 * nt + 1], al, bh[1], bh[3]);
            }

#pragma unroll
            for (int n = 0; n < 4; n++) {
                int col = wn1 + n * 8 + tg * 2;
                *(float2*)&sEe[wm1 + gg][col]     = make_float2(acc[n][0], acc[n][1]);
                *(float2*)&sEe[wm1 + gg + 8][col] = make_float2(acc[n][2], acc[n][3]);
            }
        }
        __syncthreads();

        // Phase B: warp per edge (8 warps x 4 iterations).
#pragma unroll
        for (int it = 0; it < ET1 / 8; it++) {
            int el = w * (ET1 / 8) + it;
            int e  = e0 + el;
            int src = g_src[e];
            int dst = g_dst[e];

            float4 ev = *(const float4*)&sEe[el][lane * 4];
            float4 hv = h4[src * 32 + lane];
            float m0 = fmaxf(hv.x + ev.x + bias.x, 0.f);
            float m1 = fmaxf(hv.y + ev.y + bias.y, 0.f);
            float m2 = fmaxf(hv.z + ev.z + bias.z, 0.f);
            float m3 = fmaxf(hv.w + ev.w + bias.w, 0.f);

            float* p = g_agg1 + (size_t)dst * EMB + lane * 4;
            asm volatile("red.global.add.v4.f32 [%0], {%1,%2,%3,%4};"
                         :: "l"(p), "f"(m0), "f"(m1), "f"(m2), "f"(m3)
                         : "memory");
        }
        __syncthreads();
    }
}

// ---------------------------------------------------------------------------
// K3: h1 = leaky_relu(agg1 @ W1 + b1); agg2 = (1+eps)*h1.  TENSORIZED
// (R11-validated). Block = 64 nodes, 8 warps (4m x 2n), K=128 in two halves.
// ---------------------------------------------------------------------------
#define L1S 72

__global__ void __launch_bounds__(256)
k_lin1(const float* __restrict__ b1) {
    __shared__ __align__(16) unsigned short sAh[64][L1S];
    __shared__ __align__(16) unsigned short sAl[64][L1S];
    __shared__ __align__(16) unsigned short sBh[64][L1S];
    __shared__ __align__(16) unsigned short sBl[64][L1S];

    int tid  = threadIdx.x;
    int lane = tid & 31;
    int w    = tid >> 5;
    int node0 = blockIdx.x * 64;

    int wm = (w >> 1) * 16;
    int wn = (w & 1) * 32;
    int q  = lane >> 3;
    int li = lane & 7;
    int rowoff = (q & 1) * 8 + li;
    int coloff = (q >> 1) * 8;
    int g  = lane >> 2;
    int tg = lane & 3;

    float acc[4][4];
#pragma unroll
    for (int n = 0; n < 4; n++) {
        int col = wn + n * 8 + tg * 2;
        float bb0 = b1[col];
        float bb1 = b1[col + 1];
        acc[n][0] = bb0; acc[n][1] = bb1;
        acc[n][2] = bb0; acc[n][3] = bb1;
    }

    const unsigned* wb_h = (const unsigned*)g_w1bh;   // [64 n][64 u32]
    const unsigned* wb_l = (const unsigned*)g_w1bl;

#pragma unroll
    for (int kh = 0; kh < 2; kh++) {
        if (kh) __syncthreads();
#pragma unroll
        for (int i = 0; i < 4; i++) {
            int lin = tid + i * 256;
            int nd  = lin >> 4;
            int c4  = lin & 15;
            float4 v = *(const float4*)&g_agg1[(size_t)(node0 + nd) * EMB + kh * 64 + c4 * 4];
            unsigned short h_[4], l_[4];
            float vv[4] = {v.x, v.y, v.z, v.w};
#pragma unroll
            for (int j = 0; j < 4; j++) bf16split(vv[j], h_[j], l_[j]);
            *(uint2*)&sAh[nd][c4 * 4] = *(uint2*)h_;
            *(uint2*)&sAl[nd][c4 * 4] = *(uint2*)l_;
        }
#pragma unroll
        for (int i = 0; i < 8; i++) {
            int lin = tid + i * 256;          // 0..2047
            int n   = lin >> 5;
            int c2  = lin & 31;
            ((unsigned*)&sBh[n][c2 * 2])[0] = wb_h[n * 64 + kh * 32 + c2];
            ((unsigned*)&sBl[n][c2 * 2])[0] = wb_l[n * 64 + kh * 32 + c2];
        }
        __syncthreads();

#pragma unroll
        for (int ks = 0; ks < 4; ks++) {
            unsigned ah[4], al[4];
            ldx4(ah, (unsigned)__cvta_generic_to_shared(&sAh[wm + rowoff][ks * 16 + coloff]));
            ldx4(al, (unsigned)__cvta_generic_to_shared(&sAl[wm + rowoff][ks * 16 + coloff]));
#pragma unroll
            for (int nt = 0; nt < 2; nt++) {
                unsigned bh[4], bl[4];
                ldx4(bh, (unsigned)__cvta_generic_to_shared(&sBh[wn + nt * 16 + rowoff][ks * 16 + coloff]));
                ldx4(bl, (unsigned)__cvta_generic_to_shared(&sBl[wn + nt * 16 + rowoff][ks * 16 + coloff]));
                mma16816(acc[2 * nt],     ah, bh[0], bh[2]);
                mma16816(acc[2 * nt],     ah, bl[0], bl[2]);
                mma16816(acc[2 * nt],     al, bh[0], bh[2]);
                mma16816(acc[2 * nt + 1], ah, bh[1], bh[3]);
                mma16816(acc[2 * nt + 1], ah, bl[1], bl[3]);
                mma16816(acc[2 * nt + 1], al, bh[1], bh[3]);
            }
        }
    }

#pragma unroll
    for (int n = 0; n < 4; n++) {
        int col = wn + n * 8 + tg * 2;
        float v0 = acc[n][0], v1 = acc[n][1], v2 = acc[n][2], v3 = acc[n][3];
        float a0 = v0 >= 0.f ? v0 : SLOPEF * v0;
        float a1 = v1 >= 0.f ? v1 : SLOPEF * v1;
        float a2 = v2 >= 0.f ? v2 : SLOPEF * v2;
        float a3 = v3 >= 0.f ? v3 : SLOPEF * v3;
        size_t r0 = (size_t)(node0 + wm + g) * D1 + col;
        size_t r1 = (size_t)(node0 + wm + g + 8) * D1 + col;
        *(float2*)&g_h1[r0]   = make_float2(a0, a1);
        *(float2*)&g_h1[r1]   = make_float2(a2, a3);
        *(float2*)&g_agg2[r0] = make_float2((1.f + EPSF) * a0, (1.f + EPSF) * a1);
        *(float2*)&g_agg2[r1] = make_float2((1.f + EPSF) * a2, (1.f + EPSF) * a3);
    }
}

// ---------------------------------------------------------------------------
// K4: edge pass 2, tensorized, PERSISTENT. 888 blocks over 64-edge tiles.
// Inner code identical to R12/R14.
// ---------------------------------------------------------------------------
#define ET   64
#define EESTRIDE2 68

__global__ void __launch_bounds__(256, 6)
k_edge2(const float4* __restrict__ ea4,
        const float2* __restrict__ b2v) {  // E2b as 32 float2
    __shared__ __align__(16) unsigned short sEaH[ET][16];
    __shared__ __align__(16) unsigned short sEaL[ET][16];
    __shared__ __align__(16) unsigned short sW2H[D1][16];
    __shared__ __align__(16) unsigned short sW2L[D1][16];
    __shared__ __align__(16) float sEe[ET][EESTRIDE2];

    int tid  = threadIdx.x;
    int lane = tid & 31;
    int w    = tid >> 5;

    float2 bias = b2v[lane];

    // Stage weights ONCE per persistent block.
    {
        const unsigned* wh = (const unsigned*)g_w2hi;
        const unsigned* wl = (const unsigned*)g_w2lo;
        unsigned* dh = (unsigned*)sW2H;
        unsigned* dl = (unsigned*)sW2L;
        for (int i = tid; i < D1 * 8; i += 256) { dh[i] = wh[i]; dl[i] = wl[i]; }
    }

    int wm = (w >> 1) * 16;
    int wn = (w & 1) * 32;
    int q  = lane >> 3;
    int li = lane & 7;
    int rowoff = (q & 1) * 8 + li;
    int coloff = (q >> 1) * 8;
    int gg = lane >> 2;
    int tg = lane & 3;

    const float2* h2v = (const float2*)g_h1;

    for (int tile = blockIdx.x; tile < NE / ET; tile += PBLOCKS) {
        int e0 = tile * ET;

        {
            int el = tid >> 2;
            int pt = tid & 3;
            float4 v = ea4[(size_t)(e0 + el) * 4 + pt];
            unsigned short h_[4], l_[4];
            float vv[4] = {v.x, v.y, v.z, v.w};
#pragma unroll
            for (int i = 0; i < 4; i++) bf16split(vv[i], h_[i], l_[i]);
            *(uint2*)&sEaH[el][pt * 4] = *(uint2*)h_;
            *(uint2*)&sEaL[el][pt * 4] = *(uint2*)l_;
        }
        __syncthreads();

        {
            unsigned ah[4], al[4];
            ldx4(ah, (unsigned)__cvta_generic_to_shared(&sEaH[wm + rowoff][coloff]));
            ldx4(al, (unsigned)__cvta_generic_to_shared(&sEaL[wm + rowoff][coloff]));

            float acc[4][4];
#pragma unroll
            for (int n = 0; n < 4; n++)
#pragma unroll
                for (int p = 0; p < 4; p++) acc[n][p] = 0.f;

#pragma unroll
            for (int nt = 0; nt < 2; nt++) {
                unsigned bh[4], bl[4];
                ldx4(bh, (unsigned)__cvta_generic_to_shared(&sW2H[wn + nt * 16 + rowoff][coloff]));
                ldx4(bl, (unsigned)__cvta_generic_to_shared(&sW2L[wn + nt * 16 + rowoff][coloff]));
                mma16816(acc[2 * nt],     ah, bh[0], bh[2]);
                mma16816(acc[2 * nt],     ah, bl[0], bl[2]);
                mma16816(acc[2 * nt],     al, bh[0], bh[2]);
                mma16816(acc[2 * nt + 1], ah, bh[1], bh[3]);
                mma16816(acc[2 * nt + 1], ah, bl[1], bl[3]);
                mma16816(acc[2 * nt + 1], al, bh[1], bh[3]);
            }

#pragma unroll
            for (int n = 0; n < 4; n++) {
                int col = wn + n * 8 + tg * 2;
                *(float2*)&sEe[wm + gg][col]     = make_float2(acc[n][0], acc[n][1]);
                *(float2*)&sEe[wm + gg + 8][col] = make_float2(acc[n][2], acc[n][3]);
            }
        }
        __syncthreads();

#pragma unroll
        for (int it = 0; it < ET / 8; it++) {
            int el = w * (ET / 8) + it;
            int e  = e0 + el;
            int src = g_src[e];
            int dst = g_dst[e];

            float2 ev = *(const float2*)&sEe[el][lane * 2];
            float2 hv = h2v[src * 32 + lane];
            float m0 = fmaxf(hv.x + ev.x + bias.x, 0.f);
            float m1 = fmaxf(hv.y + ev.y + bias.y, 0.f);

            float* p = g_agg2 + (size_t)dst * D1 + lane * 2;
            asm volatile("red.global.add.v2.f32 [%0], {%1,%2};"
                         :: "l"(p), "f"(m0), "f"(m1)
                         : "memory");
        }
        __syncthreads();
    }
}

// ---------------------------------------------------------------------------
// K5: h2 = agg2 @ W2 + b2, stored as bf16 hi + bf16 lo residual.
// ---------------------------------------------------------------------------
__global__ void __launch_bounds__(256)
k_lin2(const float* __restrict__ W2, const float* __restrict__ b2) {
    __shared__ float sW[D1][D2 + 1];
    __shared__ float srow[8][D1 + 4];

    int tid  = threadIdx.x;
    int warp = tid >> 5;
    int lane = tid & 31;

    for (int i = tid; i < D1 * D2; i += 256)
        sW[i >> 5][i & 31] = W2[i];

    int n = blockIdx.x * 8 + warp;
    float2 rv = *(const float2*)(g_agg2 + (size_t)n * D1 + lane * 2);
    srow[warp][lane * 2]     = rv.x;
    srow[warp][lane * 2 + 1] = rv.y;
    __syncthreads();

    float acc = b2[lane];
#pragma unroll
    for (int k = 0; k < D1; k++)
        acc = fmaf(srow[warp][k], sW[k][lane], acc);

    unsigned short h, l;
    bf16split(acc, h, l);
    g_h2hi[(size_t)n * D2 + lane] = h;
    g_h2lo[(size_t)n * D2 + lane] = l;
}

// ---------------------------------------------------------------------------
// K6: C = h2 @ h2^T via bf16 tensor cores, uint4 staging. SYMMETRIC
// (R12-validated).
// ---------------------------------------------------------------------------
#define SROW 40

__global__ void __launch_bounds__(256)
k_gemm(float* __restrict__ C) {
    int bi = blockIdx.y;
    int bj = blockIdx.x;
    if (bj < bi) return;

    __shared__ __align__(16) unsigned short Ah[128 * SROW];
    __shared__ __align__(16) unsigned short Al[128 * SROW];
    __shared__ __align__(16) unsigned short Bh[128 * SROW];
    __shared__ __align__(16) unsigned short Bl[128 * SROW];

    int tid = threadIdx.x;

    {
        const uint4* h2h4 = (const uint4*)g_h2hi;
        const uint4* h2l4 = (const uint4*)g_h2lo;
        uint4* Ah4 = (uint4*)Ah;
        uint4* Al4 = (uint4*)Al;
        uint4* Bh4 = (uint4*)Bh;
        uint4* Bl4 = (uint4*)Bl;
#pragma unroll
        for (int i = 0; i < 2; i++) {
            int idx = tid + i * 256;       // 0..511
            int r = idx >> 2;
            int q = idx & 3;
            int sm = r * 5 + q;
            Ah4[sm] = h2h4[(size_t)(bi * 128 + r) * 4 + q];
            Al4[sm] = h2l4[(size_t)(bi * 128 + r) * 4 + q];
            Bh4[sm] = h2h4[(size_t)(bj * 128 + r) * 4 + q];
            Bl4[sm] = h2l4[(size_t)(bj * 128 + r) * 4 + q];
        }
    }
    __syncthreads();

    int w    = tid >> 5;
    int lane = tid & 31;
    int wm   = (w >> 1) * 32;
    int wn   = (w & 1) * 64;
    int q    = lane >> 3;
    int li   = lane & 7;
    int rowoff = (q & 1) * 8 + li;
    int coloff = (q >> 1) * 8;

    float acc[2][8][4];
#pragma unroll
    for (int mt = 0; mt < 2; mt++)
#pragma unroll
        for (int n = 0; n < 8; n++)
#pragma unroll
            for (int p = 0; p < 4; p++) acc[mt][n][p] = 0.f;

#pragma unroll
    for (int ks = 0; ks < 2; ks++) {
        unsigned ah[2][4], al[2][4];
#pragma unroll
        for (int mt = 0; mt < 2; mt++) {
            int off = (wm + mt * 16 + rowoff) * SROW + ks * 16 + coloff;
            ldx4(ah[mt], (unsigned)__cvta_generic_to_shared(&Ah[off]));
            ldx4(al[mt], (unsigned)__cvta_generic_to_shared(&Al[off]));
        }
#pragma unroll
        for (int nt = 0; nt < 4; nt++) {
            int off = (wn + nt * 16 + rowoff) * SROW + ks * 16 + coloff;
            unsigned bh[4], bl[4];
            ldx4(bh, (unsigned)__cvta_generic_to_shared(&Bh[off]));
            ldx4(bl, (unsigned)__cvta_generic_to_shared(&Bl[off]));
#pragma unroll
            for (int mt = 0; mt < 2; mt++) {
                mma16816(acc[mt][2 * nt],     ah[mt], bh[0], bh[2]);
                mma16816(acc[mt][2 * nt],     ah[mt], bl[0], bl[2]);
                mma16816(acc[mt][2 * nt],     al[mt], bh[0], bh[2]);
                mma16816(acc[mt][2 * nt + 1], ah[mt], bh[1], bh[3]);
                mma16816(acc[mt][2 * nt + 1], ah[mt], bl[1], bl[3]);
                mma16816(acc[mt][2 * nt + 1], al[mt], bh[1], bh[3]);
            }
        }
    }

    int g  = lane >> 2;
    int tg = lane & 3;
#pragma unroll
    for (int mt = 0; mt < 2; mt++) {
        int row0 = bi * 128 + wm + mt * 16 + g;
#pragma unroll
        for (int n = 0; n < 8; n++) {
            int col = bj * 128 + wn + n * 8 + tg * 2;
            float2* p0 = (float2*)(C + (size_t)row0 * NN + col);
            float2* p1 = (float2*)(C + (size_t)(row0 + 8) * NN + col);
            *p0 = make_float2(acc[mt][n][0], acc[mt][n][1]);
            *p1 = make_float2(acc[mt][n][2], acc[mt][n][3]);
        }
    }
    if (bi != bj) {
#pragma unroll
        for (int mt = 0; mt < 2; mt++) {
            int row0 = bi * 128 + wm + mt * 16 + g;
#pragma unroll
            for (int n = 0; n < 8; n++) {
                int col = bj * 128 + wn + n * 8 + tg * 2;
                C[(size_t)col * NN + row0]           = acc[mt][n][0];
                C[(size_t)(col + 1) * NN + row0]     = acc[mt][n][1];
                C[(size_t)col * NN + row0 + 8]       = acc[mt][n][2];
                C[(size_t)(col + 1) * NN + row0 + 8] = acc[mt][n][3];
            }
        }
    }
}

// ---------------------------------------------------------------------------
extern "C" void kernel_launch(void* const* d_in, const int* in_sizes, int n_in,
                              void* d_out, int out_size) {
    const unsigned* xbuf  = (const unsigned*)d_in[0];
    const unsigned* eibuf = (const unsigned*)d_in[1];
    const float*    ea    = (const float*)d_in[2];
    const float*    emb   = (const float*)d_in[3];
    const float*    W1    = (const float*)d_in[4];
    const float*    b1    = (const float*)d_in[5];
    const float*    E1w   = (const float*)d_in[6];
    const float*    E1b   = (const float*)d_in[7];
    const float*    W2    = (const float*)d_in[8];
    const float*    b2    = (const float*)d_in[9];
    const float*    E2w   = (const float*)d_in[10];
    const float*    E2b   = (const float*)d_in[11];
    float* out = (float*)d_out;

    k_convert<<<(NE + 255) / 256, 256>>>(xbuf, eibuf);      // idx 0
    k_embed<<<NN * 32 / 256, 256>>>((const float4*)emb);    // idx 1
    k_prepw<<<8, 256>>>(E1w);                               // idx 2
    k_edge1<<<PBLOCKS, 256>>>((const float4*)ea,            // idx 3 (profiled)
                              (const float4*)E1b);
    k_prepw1<<<32, 256>>>(W1);
    k_lin1<<<NN / 64, 256>>>(b1);
    k_prepw2<<<4, 256>>>(E2w);
    k_edge2<<<PBLOCKS, 256>>>((const float4*)ea,
                              (const float2*)E2b);
    k_lin2<<<NN / 8, 256>>>(W2, b2);
    dim3 g(NN / 128, NN / 128);
    k_gemm<<<g, 256>>>(out);
}

// round 16
// speedup vs baseline: 1.4076x; 1.0129x over previous
#include <cuda_runtime.h>
#include <cuda_bf16.h>

// GINE-conv network:
//   h = emb[x]; h = leaky_relu(gine(h, E1)); h2 = gine(h, E2); out = h2 @ h2.T
// N=8192, E=262144, dims 128 -> 64 -> 32, out 8192x8192 f32.
// R16 vs R15 (157.8us): edge1 Phase-B gather eliminated. h[src]=emb[x[src]]
// and emb is only 20x128 (10KB) -> keep the whole table in smem (staged once
// per persistent block) and index by precomputed g_xsrc[e]=x[src[e]].
// Removes 134MB of L1/L2 gather traffic (half of edge1's measured cost).
// g_h buffer removed entirely. Everything else identical to R15.

#define NN     8192
#define NE     262144
#define EMB    128
#define D1     64
#define D2     32
#define NEMB   20
#define EPSF   1e-9f
#define SLOPEF 0.01f

#define PBLOCKS 888   // 148 SMs x 6 resident blocks

__device__ __align__(16) float g_agg1[NN * EMB];
__device__ __align__(16) float g_h1[NN * D1];
__device__ __align__(16) float g_agg2[NN * D1];
__device__ __align__(16) unsigned short g_h2hi[NN * D2];   // bf16 hi
__device__ __align__(16) unsigned short g_h2lo[NN * D2];   // bf16 lo residual
__device__ __align__(16) unsigned short g_w1hi[EMB * 16];  // E1w^T hi [n][k]
__device__ __align__(16) unsigned short g_w1lo[EMB * 16];  // E1w^T lo [n][k]
__device__ __align__(16) unsigned short g_w2hi[D1 * 16];   // E2w^T hi [n][k]
__device__ __align__(16) unsigned short g_w2lo[D1 * 16];   // E2w^T lo [n][k]
__device__ __align__(16) unsigned short g_w1bh[D1 * EMB];  // W1^T hi [n][k]
__device__ __align__(16) unsigned short g_w1bl[D1 * EMB];  // W1^T lo [n][k]
__device__ int g_x[NN];
__device__ int g_src[NE];
__device__ int g_dst[NE];
__device__ int g_xsrc[NE];   // x[src[e]]  (0..19)

__device__ __forceinline__ void ldx4(unsigned r[4], unsigned addr) {
    asm volatile("ldmatrix.sync.aligned.m8n8.x4.shared.b16 {%0,%1,%2,%3}, [%4];"
                 : "=r"(r[0]), "=r"(r[1]), "=r"(r[2]), "=r"(r[3]) : "r"(addr));
}
__device__ __forceinline__ void mma16816(float c[4], const unsigned a[4],
                                         unsigned b0, unsigned b1) {
    asm volatile(
        "mma.sync.aligned.m16n8k16.row.col.f32.bf16.bf16.f32 "
        "{%0,%1,%2,%3}, {%4,%5,%6,%7}, {%8,%9}, {%0,%1,%2,%3};"
        : "+f"(c[0]), "+f"(c[1]), "+f"(c[2]), "+f"(c[3])
        : "r"(a[0]), "r"(a[1]), "r"(a[2]), "r"(a[3]), "r"(b0), "r"(b1));
}
__device__ __forceinline__ void bf16split(float v, unsigned short& h,
                                          unsigned short& l) {
    __nv_bfloat16 hi = __float2bfloat16_rn(v);
    float res = v - __bfloat162float(hi);
    __nv_bfloat16 lo = __float2bfloat16_rn(res);
    h = *(unsigned short*)&hi;
    l = *(unsigned short*)&lo;
}

// ---------------------------------------------------------------------------
// K0: normalize index dtypes (int64 vs int32 delivery; detection as before).
// ---------------------------------------------------------------------------
__global__ void k_convert(const unsigned* __restrict__ xbuf,
                          const unsigned* __restrict__ eibuf) {
    unsigned odd_or = 0;
#pragma unroll
    for (int i = 0; i < 32; i++) odd_or |= eibuf[2 * i + 1];
    bool mode64 = (odd_or == 0);

    int t = blockIdx.x * blockDim.x + threadIdx.x;
    if (t < NE) {
        g_src[t] = (int)(mode64 ? eibuf[2 * t]        : eibuf[t]);
        g_dst[t] = (int)(mode64 ? eibuf[2 * (NE + t)] : eibuf[NE + t]);
    }
    if (t < NN) g_x[t] = (int)(mode64 ? xbuf[2 * t] : xbuf[t]);
}

// ---------------------------------------------------------------------------
// K1: agg1 = (1+eps)*emb[x]  AND  g_xsrc[e] = x[src[e]].
// Grid covers exactly NN*32 = NE = 262144 threads.
// ---------------------------------------------------------------------------
__global__ void k_embed(const float4* __restrict__ emb4) {
    int t = blockIdx.x * blockDim.x + threadIdx.x;
    int node = t >> 5;
    int c    = t & 31;
    float4 v = emb4[g_x[node] * 32 + c];
    float4 a = make_float4(v.x * (1.f + EPSF), v.y * (1.f + EPSF),
                           v.z * (1.f + EPSF), v.w * (1.f + EPSF));
    ((float4*)g_agg1)[t] = a;
    g_xsrc[t] = g_x[g_src[t]];
}

// ---------------------------------------------------------------------------
// Weight prep kernels (bf16 hi/lo transposed splits).
// ---------------------------------------------------------------------------
__global__ void k_prepw(const float* __restrict__ E1w) {
    int t = blockIdx.x * blockDim.x + threadIdx.x;   // 0..2047
    int n = t >> 4;
    int k = t & 15;
    unsigned short h, l;
    bf16split(E1w[k * EMB + n], h, l);
    g_w1hi[t] = h;
    g_w1lo[t] = l;
}

__global__ void k_prepw2(const float* __restrict__ E2w) {
    int t = blockIdx.x * blockDim.x + threadIdx.x;   // 0..1023
    int n = t >> 4;
    int k = t & 15;
    unsigned short h, l;
    bf16split(E2w[k * D1 + n], h, l);
    g_w2hi[t] = h;
    g_w2lo[t] = l;
}

// W1 [128 k][64 n] -> W1^T hi/lo [64 n][128 k]
__global__ void k_prepw1(const float* __restrict__ W1) {
    int t = blockIdx.x * blockDim.x + threadIdx.x;   // 0..8191
    int n = t >> 7;
    int kk = t & 127;
    unsigned short h, l;
    bf16split(W1[kk * D1 + n], h, l);
    g_w1bh[t] = h;
    g_w1bl[t] = l;
}

// ---------------------------------------------------------------------------
// K2: edge pass 1, PERSISTENT, smem-resident emb table.
// Phase B gathers h[src] from the 10KB smem emb table via g_xsrc (broadcast
// LDS) instead of 512B global rows -> 134MB less L1/L2 traffic.
// ---------------------------------------------------------------------------
#define ET1  32
#define EESTRIDE 132

__global__ void __launch_bounds__(256, 6)
k_edge1(const float4* __restrict__ ea4,
        const float4* __restrict__ emb4,
        const float4* __restrict__ b4) {   // E1b as 32 float4
    __shared__ __align__(16) unsigned short sEaH[ET1][16];
    __shared__ __align__(16) unsigned short sEaL[ET1][16];
    __shared__ __align__(16) unsigned short sWtH[EMB][16];
    __shared__ __align__(16) unsigned short sWtL[EMB][16];
    __shared__ __align__(16) float sEe[ET1][EESTRIDE];
    __shared__ __align__(16) float4 sEmb[NEMB * 32];   // 10KB emb table

    int tid  = threadIdx.x;
    int lane = tid & 31;
    int w    = tid >> 5;

    float4 bias = b4[lane];

    // Stage weights + emb table ONCE per persistent block.
    {
        const unsigned* wh = (const unsigned*)g_w1hi;
        const unsigned* wl = (const unsigned*)g_w1lo;
        unsigned* dh = (unsigned*)sWtH;
        unsigned* dl = (unsigned*)sWtL;
        for (int i = tid; i < EMB * 8; i += 256) { dh[i] = wh[i]; dl[i] = wl[i]; }
        for (int i = tid; i < NEMB * 32; i += 256) sEmb[i] = emb4[i];
    }

    int wm1 = (w >> 2) * 16;
    int wn1 = (w & 3) * 32;
    int q   = lane >> 3;
    int li  = lane & 7;
    int rowoff = (q & 1) * 8 + li;
    int coloff = (q >> 1) * 8;
    int gg  = lane >> 2;
    int tg  = lane & 3;

    for (int tile = blockIdx.x; tile < NE / ET1; tile += PBLOCKS) {
        int e0 = tile * ET1;

        if (tid < ET1 * 4) {
            int el = tid >> 2;
            int pt = tid & 3;
            float4 v = ea4[(size_t)(e0 + el) * 4 + pt];
            unsigned short h_[4], l_[4];
            float vv[4] = {v.x, v.y, v.z, v.w};
#pragma unroll
            for (int i = 0; i < 4; i++) bf16split(vv[i], h_[i], l_[i]);
            *(uint2*)&sEaH[el][pt * 4] = *(uint2*)h_;
            *(uint2*)&sEaL[el][pt * 4] = *(uint2*)l_;
        }
        __syncthreads();

        // Phase A
        {
            unsigned ah[4], al[4];
            ldx4(ah, (unsigned)__cvta_generic_to_shared(&sEaH[wm1 + rowoff][coloff]));
            ldx4(al, (unsigned)__cvta_generic_to_shared(&sEaL[wm1 + rowoff][coloff]));

            float acc[4][4];
#pragma unroll
            for (int n = 0; n < 4; n++)
#pragma unroll
                for (int p = 0; p < 4; p++) acc[n][p] = 0.f;

#pragma unroll
            for (int nt = 0; nt < 2; nt++) {
                unsigned bh[4], bl[4];
                ldx4(bh, (unsigned)__cvta_generic_to_shared(&sWtH[wn1 + nt * 16 + rowoff][coloff]));
                ldx4(bl, (unsigned)__cvta_generic_to_shared(&sWtL[wn1 + nt * 16 + rowoff][coloff]));
                mma16816(acc[2 * nt],     ah, bh[0], bh[2]);
                mma16816(acc[2 * nt],     ah, bl[0], bl[2]);
                mma16816(acc[2 * nt],     al, bh[0], bh[2]);
                mma16816(acc[2 * nt + 1], ah, bh[1], bh[3]);
                mma16816(acc[2 * nt + 1], ah, bl[1], bl[3]);
                mma16816(acc[2 * nt + 1], al, bh[1], bh[3]);
            }

#pragma unroll
            for (int n = 0; n < 4; n++) {
                int col = wn1 + n * 8 + tg * 2;
                *(float2*)&sEe[wm1 + gg][col]     = make_float2(acc[n][0], acc[n][1]);
                *(float2*)&sEe[wm1 + gg + 8][col] = make_float2(acc[n][2], acc[n][3]);
            }
        }
        __syncthreads();

        // Phase B: warp per edge; h[src] from smem emb table.
#pragma unroll
        for (int it = 0; it < ET1 / 8; it++) {
            int el = w * (ET1 / 8) + it;
            int e  = e0 + el;
            int xs = g_xsrc[e];
            int dst = g_dst[e];

            float4 ev = *(const float4*)&sEe[el][lane * 4];
            float4 hv = sEmb[xs * 32 + lane];
            float m0 = fmaxf(hv.x + ev.x + bias.x, 0.f);
            float m1 = fmaxf(hv.y + ev.y + bias.y, 0.f);
            float m2 = fmaxf(hv.z + ev.z + bias.z, 0.f);
            float m3 = fmaxf(hv.w + ev.w + bias.w, 0.f);

            float* p = g_agg1 + (size_t)dst * EMB + lane * 4;
            asm volatile("red.global.add.v4.f32 [%0], {%1,%2,%3,%4};"
                         :: "l"(p), "f"(m0), "f"(m1), "f"(m2), "f"(m3)
                         : "memory");
        }
        __syncthreads();
    }
}

// ---------------------------------------------------------------------------
// K3: h1 = leaky_relu(agg1 @ W1 + b1); agg2 = (1+eps)*h1.  TENSORIZED
// (R11-validated).
// ---------------------------------------------------------------------------
#define L1S 72

__global__ void __launch_bounds__(256)
k_lin1(const float* __restrict__ b1) {
    __shared__ __align__(16) unsigned short sAh[64][L1S];
    __shared__ __align__(16) unsigned short sAl[64][L1S];
    __shared__ __align__(16) unsigned short sBh[64][L1S];
    __shared__ __align__(16) unsigned short sBl[64][L1S];

    int tid  = threadIdx.x;
    int lane = tid & 31;
    int w    = tid >> 5;
    int node0 = blockIdx.x * 64;

    int wm = (w >> 1) * 16;
    int wn = (w & 1) * 32;
    int q  = lane >> 3;
    int li = lane & 7;
    int rowoff = (q & 1) * 8 + li;
    int coloff = (q >> 1) * 8;
    int g  = lane >> 2;
    int tg = lane & 3;

    float acc[4][4];
#pragma unroll
    for (int n = 0; n < 4; n++) {
        int col = wn + n * 8 + tg * 2;
        float bb0 = b1[col];
        float bb1 = b1[col + 1];
        acc[n][0] = bb0; acc[n][1] = bb1;
        acc[n][2] = bb0; acc[n][3] = bb1;
    }

    const unsigned* wb_h = (const unsigned*)g_w1bh;   // [64 n][64 u32]
    const unsigned* wb_l = (const unsigned*)g_w1bl;

#pragma unroll
    for (int kh = 0; kh < 2; kh++) {
        if (kh) __syncthreads();
#pragma unroll
        for (int i = 0; i < 4; i++) {
            int lin = tid + i * 256;
            int nd  = lin >> 4;
            int c4  = lin & 15;
            float4 v = *(const float4*)&g_agg1[(size_t)(node0 + nd) * EMB + kh * 64 + c4 * 4];
            unsigned short h_[4], l_[4];
            float vv[4] = {v.x, v.y, v.z, v.w};
#pragma unroll
            for (int j = 0; j < 4; j++) bf16split(vv[j], h_[j], l_[j]);
            *(uint2*)&sAh[nd][c4 * 4] = *(uint2*)h_;
            *(uint2*)&sAl[nd][c4 * 4] = *(uint2*)l_;
        }
#pragma unroll
        for (int i = 0; i < 8; i++) {
            int lin = tid + i * 256;          // 0..2047
            int n   = lin >> 5;
            int c2  = lin & 31;
            ((unsigned*)&sBh[n][c2 * 2])[0] = wb_h[n * 64 + kh * 32 + c2];
            ((unsigned*)&sBl[n][c2 * 2])[0] = wb_l[n * 64 + kh * 32 + c2];
        }
        __syncthreads();

#pragma unroll
        for (int ks = 0; ks < 4; ks++) {
            unsigned ah[4], al[4];
            ldx4(ah, (unsigned)__cvta_generic_to_shared(&sAh[wm + rowoff][ks * 16 + coloff]));
            ldx4(al, (unsigned)__cvta_generic_to_shared(&sAl[wm + rowoff][ks * 16 + coloff]));
#pragma unroll
            for (int nt = 0; nt < 2; nt++) {
                unsigned bh[4], bl[4];
                ldx4(bh, (unsigned)__cvta_generic_to_shared(&sBh[wn + nt * 16 + rowoff][ks * 16 + coloff]));
                ldx4(bl, (unsigned)__cvta_generic_to_shared(&sBl[wn + nt * 16 + rowoff][ks * 16 + coloff]));
                mma16816(acc[2 * nt],     ah, bh[0], bh[2]);
                mma16816(acc[2 * nt],     ah, bl[0], bl[2]);
                mma16816(acc[2 * nt],     al, bh[0], bh[2]);
                mma16816(acc[2 * nt + 1], ah, bh[1], bh[3]);
                mma16816(acc[2 * nt + 1], ah, bl[1], bl[3]);
                mma16816(acc[2 * nt + 1], al, bh[1], bh[3]);
            }
        }
    }

#pragma unroll
    for (int n = 0; n < 4; n++) {
        int col = wn + n * 8 + tg * 2;
        float v0 = acc[n][0], v1 = acc[n][1], v2 = acc[n][2], v3 = acc[n][3];
        float a0 = v0 >= 0.f ? v0 : SLOPEF * v0;
        float a1 = v1 >= 0.f ? v1 : SLOPEF * v1;
        float a2 = v2 >= 0.f ? v2 : SLOPEF * v2;
        float a3 = v3 >= 0.f ? v3 : SLOPEF * v3;
        size_t r0 = (size_t)(node0 + wm + g) * D1 + col;
        size_t r1 = (size_t)(node0 + wm + g + 8) * D1 + col;
        *(float2*)&g_h1[r0]   = make_float2(a0, a1);
        *(float2*)&g_h1[r1]   = make_float2(a2, a3);
        *(float2*)&g_agg2[r0] = make_float2((1.f + EPSF) * a0, (1.f + EPSF) * a1);
        *(float2*)&g_agg2[r1] = make_float2((1.f + EPSF) * a2, (1.f + EPSF) * a3);
    }
}

// ---------------------------------------------------------------------------
// K4: edge pass 2, tensorized, PERSISTENT (R15 structure).
// ---------------------------------------------------------------------------
#define ET   64
#define EESTRIDE2 68

__global__ void __launch_bounds__(256, 6)
k_edge2(const float4* __restrict__ ea4,
        const float2* __restrict__ b2v) {  // E2b as 32 float2
    __shared__ __align__(16) unsigned short sEaH[ET][16];
    __shared__ __align__(16) unsigned short sEaL[ET][16];
    __shared__ __align__(16) unsigned short sW2H[D1][16];
    __shared__ __align__(16) unsigned short sW2L[D1][16];
    __shared__ __align__(16) float sEe[ET][EESTRIDE2];

    int tid  = threadIdx.x;
    int lane = tid & 31;
    int w    = tid >> 5;

    float2 bias = b2v[lane];

    {
        const unsigned* wh = (const unsigned*)g_w2hi;
        const unsigned* wl = (const unsigned*)g_w2lo;
        unsigned* dh = (unsigned*)sW2H;
        unsigned* dl = (unsigned*)sW2L;
        for (int i = tid; i < D1 * 8; i += 256) { dh[i] = wh[i]; dl[i] = wl[i]; }
    }

    int wm = (w >> 1) * 16;
    int wn = (w & 1) * 32;
    int q  = lane >> 3;
    int li = lane & 7;
    int rowoff = (q & 1) * 8 + li;
    int coloff = (q >> 1) * 8;
    int gg = lane >> 2;
    int tg = lane & 3;

    const float2* h2v = (const float2*)g_h1;

    for (int tile = blockIdx.x; tile < NE / ET; tile += PBLOCKS) {
        int e0 = tile * ET;

        {
            int el = tid >> 2;
            int pt = tid & 3;
            float4 v = ea4[(size_t)(e0 + el) * 4 + pt];
            unsigned short h_[4], l_[4];
            float vv[4] = {v.x, v.y, v.z, v.w};
#pragma unroll
            for (int i = 0; i < 4; i++) bf16split(vv[i], h_[i], l_[i]);
            *(uint2*)&sEaH[el][pt * 4] = *(uint2*)h_;
            *(uint2*)&sEaL[el][pt * 4] = *(uint2*)l_;
        }
        __syncthreads();

        {
            unsigned ah[4], al[4];
            ldx4(ah, (unsigned)__cvta_generic_to_shared(&sEaH[wm + rowoff][coloff]));
            ldx4(al, (unsigned)__cvta_generic_to_shared(&sEaL[wm + rowoff][coloff]));

            float acc[4][4];
#pragma unroll
            for (int n = 0; n < 4; n++)
#pragma unroll
                for (int p = 0; p < 4; p++) acc[n][p] = 0.f;

#pragma unroll
            for (int nt = 0; nt < 2; nt++) {
                unsigned bh[4], bl[4];
                ldx4(bh, (unsigned)__cvta_generic_to_shared(&sW2H[wn + nt * 16 + rowoff][coloff]));
                ldx4(bl, (unsigned)__cvta_generic_to_shared(&sW2L[wn + nt * 16 + rowoff][coloff]));
                mma16816(acc[2 * nt],     ah, bh[0], bh[2]);
                mma16816(acc[2 * nt],     ah, bl[0], bl[2]);
                mma16816(acc[2 * nt],     al, bh[0], bh[2]);
                mma16816(acc[2 * nt + 1], ah, bh[1], bh[3]);
                mma16816(acc[2 * nt + 1], ah, bl[1], bl[3]);
                mma16816(acc[2 * nt + 1], al, bh[1], bh[3]);
            }

#pragma unroll
            for (int n = 0; n < 4; n++) {
                int col = wn + n * 8 + tg * 2;
                *(float2*)&sEe[wm + gg][col]     = make_float2(acc[n][0], acc[n][1]);
                *(float2*)&sEe[wm + gg + 8][col] = make_float2(acc[n][2], acc[n][3]);
            }
        }
        __syncthreads();

#pragma unroll
        for (int it = 0; it < ET / 8; it++) {
            int el = w * (ET / 8) + it;
            int e  = e0 + el;
            int src = g_src[e];
            int dst = g_dst[e];

            float2 ev = *(const float2*)&sEe[el][lane * 2];
            float2 hv = h2v[src * 32 + lane];
            float m0 = fmaxf(hv.x + ev.x + bias.x, 0.f);
            float m1 = fmaxf(hv.y + ev.y + bias.y, 0.f);

            float* p = g_agg2 + (size_t)dst * D1 + lane * 2;
            asm volatile("red.global.add.v2.f32 [%0], {%1,%2};"
                         :: "l"(p), "f"(m0), "f"(m1)
                         : "memory");
        }
        __syncthreads();
    }
}

// ---------------------------------------------------------------------------
// K5: h2 = agg2 @ W2 + b2, stored as bf16 hi + bf16 lo residual.
// ---------------------------------------------------------------------------
__global__ void __launch_bounds__(256)
k_lin2(const float* __restrict__ W2, const float* __restrict__ b2) {
    __shared__ float sW[D1][D2 + 1];
    __shared__ float srow[8][D1 + 4];

    int tid  = threadIdx.x;
    int warp = tid >> 5;
    int lane = tid & 31;

    for (int i = tid; i < D1 * D2; i += 256)
        sW[i >> 5][i & 31] = W2[i];

    int n = blockIdx.x * 8 + warp;
    float2 rv = *(const float2*)(g_agg2 + (size_t)n * D1 + lane * 2);
    srow[warp][lane * 2]     = rv.x;
    srow[warp][lane * 2 + 1] = rv.y;
    __syncthreads();

    float acc = b2[lane];
#pragma unroll
    for (int k = 0; k < D1; k++)
        acc = fmaf(srow[warp][k], sW[k][lane], acc);

    unsigned short h, l;
    bf16split(acc, h, l);
    g_h2hi[(size_t)n * D2 + lane] = h;
    g_h2lo[(size_t)n * D2 + lane] = l;
}

// ---------------------------------------------------------------------------
// K6: C = h2 @ h2^T via bf16 tensor cores, uint4 staging. SYMMETRIC
// (R12-validated).
// ---------------------------------------------------------------------------
#define SROW 40

__global__ void __launch_bounds__(256)
k_gemm(float* __restrict__ C) {
    int bi = blockIdx.y;
    int bj = blockIdx.x;
    if (bj < bi) return;

    __shared__ __align__(16) unsigned short Ah[128 * SROW];
    __shared__ __align__(16) unsigned short Al[128 * SROW];
    __shared__ __align__(16) unsigned short Bh[128 * SROW];
    __shared__ __align__(16) unsigned short Bl[128 * SROW];

    int tid = threadIdx.x;

    {
        const uint4* h2h4 = (const uint4*)g_h2hi;
        const uint4* h2l4 = (const uint4*)g_h2lo;
        uint4* Ah4 = (uint4*)Ah;
        uint4* Al4 = (uint4*)Al;
        uint4* Bh4 = (uint4*)Bh;
        uint4* Bl4 = (uint4*)Bl;
#pragma unroll
        for (int i = 0; i < 2; i++) {
            int idx = tid + i * 256;       // 0..511
            int r = idx >> 2;
            int q = idx & 3;
            int sm = r * 5 + q;
            Ah4[sm] = h2h4[(size_t)(bi * 128 + r) * 4 + q];
            Al4[sm] = h2l4[(size_t)(bi * 128 + r) * 4 + q];
            Bh4[sm] = h2h4[(size_t)(bj * 128 + r) * 4 + q];
            Bl4[sm] = h2l4[(size_t)(bj * 128 + r) * 4 + q];
        }
    }
    __syncthreads();

    int w    = tid >> 5;
    int lane = tid & 31;
    int wm   = (w >> 1) * 32;
    int wn   = (w & 1) * 64;
    int q    = lane >> 3;
    int li   = lane & 7;
    int rowoff = (q & 1) * 8 + li;
    int coloff = (q >> 1) * 8;

    float acc[2][8][4];
#pragma unroll
    for (int mt = 0; mt < 2; mt++)
#pragma unroll
        for (int n = 0; n < 8; n++)
#pragma unroll
            for (int p = 0; p < 4; p++) acc[mt][n][p] = 0.f;

#pragma unroll
    for (int ks = 0; ks < 2; ks++) {
        unsigned ah[2][4], al[2][4];
#pragma unroll
        for (int mt = 0; mt < 2; mt++) {
            int off = (wm + mt * 16 + rowoff) * SROW + ks * 16 + coloff;
            ldx4(ah[mt], (unsigned)__cvta_generic_to_shared(&Ah[off]));
            ldx4(al[mt], (unsigned)__cvta_generic_to_shared(&Al[off]));
        }
#pragma unroll
        for (int nt = 0; nt < 4; nt++) {
            int off = (wn + nt * 16 + rowoff) * SROW + ks * 16 + coloff;
            unsigned bh[4], bl[4];
            ldx4(bh, (unsigned)__cvta_generic_to_shared(&Bh[off]));
            ldx4(bl, (unsigned)__cvta_generic_to_shared(&Bl[off]));
#pragma unroll
            for (int mt = 0; mt < 2; mt++) {
                mma16816(acc[mt][2 * nt],     ah[mt], bh[0], bh[2]);
                mma16816(acc[mt][2 * nt],     ah[mt], bl[0], bl[2]);
                mma16816(acc[mt][2 * nt],     al[mt], bh[0], bh[2]);
                mma16816(acc[mt][2 * nt + 1], ah[mt], bh[1], bh[3]);
                mma16816(acc[mt][2 * nt + 1], ah[mt], bl[1], bl[3]);
                mma16816(acc[mt][2 * nt + 1], al[mt], bh[1], bh[3]);
            }
        }
    }

    int g  = lane >> 2;
    int tg = lane & 3;
#pragma unroll
    for (int mt = 0; mt < 2; mt++) {
        int row0 = bi * 128 + wm + mt * 16 + g;
#pragma unroll
        for (int n = 0; n < 8; n++) {
            int col = bj * 128 + wn + n * 8 + tg * 2;
            float2* p0 = (float2*)(C + (size_t)row0 * NN + col);
            float2* p1 = (float2*)(C + (size_t)(row0 + 8) * NN + col);
            *p0 = make_float2(acc[mt][n][0], acc[mt][n][1]);
            *p1 = make_float2(acc[mt][n][2], acc[mt][n][3]);
        }
    }
    if (bi != bj) {
#pragma unroll
        for (int mt = 0; mt < 2; mt++) {
            int row0 = bi * 128 + wm + mt * 16 + g;
#pragma unroll
            for (int n = 0; n < 8; n++) {
                int col = bj * 128 + wn + n * 8 + tg * 2;
                C[(size_t)col * NN + row0]           = acc[mt][n][0];
                C[(size_t)(col + 1) * NN + row0]     = acc[mt][n][1];
                C[(size_t)col * NN + row0 + 8]       = acc[mt][n][2];
                C[(size_t)(col + 1) * NN + row0 + 8] = acc[mt][n][3];
            }
        }
    }
}

// ---------------------------------------------------------------------------
extern "C" void kernel_launch(void* const* d_in, const int* in_sizes, int n_in,
                              void* d_out, int out_size) {
    const unsigned* xbuf  = (const unsigned*)d_in[0];
    const unsigned* eibuf = (const unsigned*)d_in[1];
    const float*    ea    = (const float*)d_in[2];
    const float*    emb   = (const float*)d_in[3];
    const float*    W1    = (const float*)d_in[4];
    const float*    b1    = (const float*)d_in[5];
    const float*    E1w   = (const float*)d_in[6];
    const float*    E1b   = (const float*)d_in[7];
    const float*    W2    = (const float*)d_in[8];
    const float*    b2    = (const float*)d_in[9];
    const float*    E2w   = (const float*)d_in[10];
    const float*    E2b   = (const float*)d_in[11];
    float* out = (float*)d_out;

    k_convert<<<(NE + 255) / 256, 256>>>(xbuf, eibuf);      // idx 0
    k_embed<<<NN * 32 / 256, 256>>>((const float4*)emb);    // idx 1
    k_prepw<<<8, 256>>>(E1w);                               // idx 2
    k_edge1<<<PBLOCKS, 256>>>((const float4*)ea,            // idx 3 (profiled)
                              (const float4*)emb,
                              (const float4*)E1b);
    k_prepw1<<<32, 256>>>(W1);
    k_lin1<<<NN / 64, 256>>>(b1);
    k_prepw2<<<4, 256>>>(E2w);
    k_edge2<<<PBLOCKS, 256>>>((const float4*)ea,
                              (const float2*)E2b);
    k_lin2<<<NN / 8, 256>>>(W2, b2);
    dim3 g(NN / 128, NN / 128);
    k_gemm<<<g, 256>>>(out);
}